// round 10
// baseline (speedup 1.0000x reference)
#include <cuda_runtime.h>
#include <cuda_bf16.h>
#include <cstdint>

#define KQ     12
#define D_NBR  320
#define D_NEW  256
#define HQ     8
#define DKQ    32
#define LN_EPS 1e-5f
#define BN_TOT (64 * 128)          // 8192 atoms
#define M_E    (BN_TOT * KQ)       // 98304 neighbor rows
#define NC_E   (D_NBR / 32)        // 10 k-chunks (BK=32)
#define NC_H   (D_NEW / 32)        // 8 k-chunks
#define BLK_BYTES 16384            // Wa: one (128n x 32k) hi+lo image block
#define WNC_BYTES 32768            // Wn: one (256n x 32k) hi+lo image block

// ------------------------- device scratch -------------------------
__device__ __align__(16) unsigned char g_WnImg[NC_E * WNC_BYTES];          // 320 KB
__device__ __align__(16) unsigned char g_WaImg[2 * NC_H * BLK_BYTES];      // 256 KB
__device__ float g_h[(size_t)BN_TOT * 256];

// ------------------------- helpers -------------------------
__device__ __forceinline__ uint32_t smem_u32(const void* p) {
    uint32_t a;
    asm("{ .reg .u64 t; cvta.to.shared.u64 t, %1; cvt.u32.u64 %0, t; }" : "=r"(a) : "l"(p));
    return a;
}
__device__ __forceinline__ void ldmx4(uint32_t* r, uint32_t addr) {
    asm volatile("ldmatrix.sync.aligned.m8n8.x4.shared.b16 {%0,%1,%2,%3}, [%4];"
        : "=r"(r[0]), "=r"(r[1]), "=r"(r[2]), "=r"(r[3]) : "r"(addr));
}
__device__ __forceinline__ void mma_bf16(float* d, const uint32_t* a, const uint32_t* b) {
    asm volatile(
        "mma.sync.aligned.m16n8k16.row.col.f32.bf16.bf16.f32 "
        "{%0,%1,%2,%3}, {%4,%5,%6,%7}, {%8,%9}, {%0,%1,%2,%3};"
        : "+f"(d[0]), "+f"(d[1]), "+f"(d[2]), "+f"(d[3])
        : "r"(a[0]), "r"(a[1]), "r"(a[2]), "r"(a[3]), "r"(b[0]), "r"(b[1]));
}
__device__ __forceinline__ void cp16(uint32_t saddr, const void* g) {
    asm volatile("cp.async.cg.shared.global [%0], [%1], 16;" :: "r"(saddr), "l"(g) : "memory");
}
#define CP_COMMIT() asm volatile("cp.async.commit_group;" ::: "memory")
#define CP_WAIT(n)  asm volatile("cp.async.wait_group %0;" :: "n"(n) : "memory")

// swizzled offset inside an (R rows x 32k) bf16 image (row-major rows of 64B)
__device__ __host__ __forceinline__ uint32_t swz(int r, int k) {
    return (uint32_t)(r * 64 + ((((k >> 3) ^ ((r >> 1) & 3))) << 4) + (k & 7) * 2);
}
__device__ __forceinline__ uint32_t pack_bf2(float a, float b) {
    __nv_bfloat162 p = __floats2bfloat162_rn(a, b);
    return *(uint32_t*)&p;
}

// ------------------------- prep: split W into bf16 hi/lo swizzled images -------------------------
__global__ void prep_w(const float* __restrict__ Wn, const float* __restrict__ Wa) {
    int i = blockIdx.x * blockDim.x + threadIdx.x;
    if (i < D_NBR * 256) {
        // Wn: full-width image, [kc] -> (256n x 32k) hi + lo
        const int k = i >> 8, n = i & 255;
        const int kc = k >> 5, kl = k & 31;
        const float x = Wn[k * 256 + n];
        const __nv_bfloat16 hi = __float2bfloat16(x);
        const __nv_bfloat16 lo = __float2bfloat16(x - __bfloat162float(hi));
        unsigned char* base = g_WnImg + (size_t)kc * WNC_BYTES;
        const uint32_t off = swz(n, kl);
        *(__nv_bfloat16*)(base + off)         = hi;
        *(__nv_bfloat16*)(base + 16384 + off) = lo;
    } else if (i < (D_NBR + D_NEW) * 256) {
        // Wa: old layout, [ntile][kc] -> (128n x 32k) hi + lo
        const int idx = i - D_NBR * 256;
        const int k = idx >> 8, n = idx & 255;
        const int ntile = n >> 7, nl = n & 127, kc = k >> 5, kl = k & 31;
        const float x = Wa[k * 256 + n];
        const __nv_bfloat16 hi = __float2bfloat16(x);
        const __nv_bfloat16 lo = __float2bfloat16(x - __bfloat162float(hi));
        unsigned char* base = g_WaImg + (size_t)(ntile * NC_H + kc) * BLK_BYTES;
        const uint32_t off = swz(nl, kl);
        *(__nv_bfloat16*)(base + off)        = hi;
        *(__nv_bfloat16*)(base + 8192 + off) = lo;
    }
}

// ------------------------- h-GEMM (bf16x3 mma): g_h = atom @ Wa + ba -------------------------
__global__ void __launch_bounds__(256, 2)
gemm_h(const float* __restrict__ X, const float* __restrict__ bias)
{
    extern __shared__ unsigned char sm[];
    const int t = threadIdx.x;
    const int lane = t & 31, wid = t >> 5;
    const int m0 = blockIdx.x * 128;
    const int nblk = blockIdx.y;
    const int K = D_NEW, NC = NC_H;

    const uint32_t sA = smem_u32(sm);
    const uint32_t sB = sA + 32768;

    const int wm = (wid & 3) * 32;
    const int wn = (wid >> 2) * 64;
    const int laneMA  = (lane & 7) + ((lane >> 3) & 1) * 8;
    const int laneK8A = lane >> 4;
    const int laneNB  = (lane & 7) + ((lane >> 4) & 1) * 8;
    const int laneK8B = (lane >> 3) & 1;

    float acc[2][8][4];
    #pragma unroll
    for (int mt = 0; mt < 2; ++mt)
        #pragma unroll
        for (int ng = 0; ng < 8; ++ng)
            #pragma unroll
            for (int j = 0; j < 4; ++j) acc[mt][ng][j] = 0.f;

    const int srow = t >> 1, shalf = t & 1;
    const float* Xrow = X + (size_t)(m0 + srow) * K + shalf * 16;
    const uint32_t offH0 = swz(srow, shalf * 16);
    const uint32_t offH1 = swz(srow, shalf * 16 + 8);

    float4 pf[4];
    #define LDA(kc) do { \
        const float4* xp = (const float4*)(Xrow + (kc) * 32); \
        pf[0] = xp[0]; pf[1] = xp[1]; pf[2] = xp[2]; pf[3] = xp[3]; } while (0)

    #define CVTSTS(st, abase, lodelta) do { \
        uint32_t ab = (abase); \
        uint4 hi0, lo0, hi1, lo1; \
        hi0.x = pack_bf2(pf[0].x, pf[0].y); hi0.y = pack_bf2(pf[0].z, pf[0].w); \
        hi0.z = pack_bf2(pf[1].x, pf[1].y); hi0.w = pack_bf2(pf[1].z, pf[1].w); \
        hi1.x = pack_bf2(pf[2].x, pf[2].y); hi1.y = pack_bf2(pf[2].z, pf[2].w); \
        hi1.z = pack_bf2(pf[3].x, pf[3].y); hi1.w = pack_bf2(pf[3].z, pf[3].w); \
        lo0.x = pack_bf2(pf[0].x - __bfloat162float(__float2bfloat16(pf[0].x)), \
                         pf[0].y - __bfloat162float(__float2bfloat16(pf[0].y))); \
        lo0.y = pack_bf2(pf[0].z - __bfloat162float(__float2bfloat16(pf[0].z)), \
                         pf[0].w - __bfloat162float(__float2bfloat16(pf[0].w))); \
        lo0.z = pack_bf2(pf[1].x - __bfloat162float(__float2bfloat16(pf[1].x)), \
                         pf[1].y - __bfloat162float(__float2bfloat16(pf[1].y))); \
        lo0.w = pack_bf2(pf[1].z - __bfloat162float(__float2bfloat16(pf[1].z)), \
                         pf[1].w - __bfloat162float(__float2bfloat16(pf[1].w))); \
        lo1.x = pack_bf2(pf[2].x - __bfloat162float(__float2bfloat16(pf[2].x)), \
                         pf[2].y - __bfloat162float(__float2bfloat16(pf[2].y))); \
        lo1.y = pack_bf2(pf[2].z - __bfloat162float(__float2bfloat16(pf[2].z)), \
                         pf[2].w - __bfloat162float(__float2bfloat16(pf[2].w))); \
        lo1.z = pack_bf2(pf[3].x - __bfloat162float(__float2bfloat16(pf[3].x)), \
                         pf[3].y - __bfloat162float(__float2bfloat16(pf[3].y))); \
        lo1.w = pack_bf2(pf[3].z - __bfloat162float(__float2bfloat16(pf[3].z)), \
                         pf[3].w - __bfloat162float(__float2bfloat16(pf[3].w))); \
        asm volatile("st.shared.v4.b32 [%0], {%1,%2,%3,%4};" :: "r"(ab + offH0), \
            "r"(hi0.x), "r"(hi0.y), "r"(hi0.z), "r"(hi0.w) : "memory"); \
        asm volatile("st.shared.v4.b32 [%0], {%1,%2,%3,%4};" :: "r"(ab + offH1), \
            "r"(hi1.x), "r"(hi1.y), "r"(hi1.z), "r"(hi1.w) : "memory"); \
        asm volatile("st.shared.v4.b32 [%0], {%1,%2,%3,%4};" :: "r"(ab + (lodelta) + offH0), \
            "r"(lo0.x), "r"(lo0.y), "r"(lo0.z), "r"(lo0.w) : "memory"); \
        asm volatile("st.shared.v4.b32 [%0], {%1,%2,%3,%4};" :: "r"(ab + (lodelta) + offH1), \
            "r"(lo1.x), "r"(lo1.y), "r"(lo1.z), "r"(lo1.w) : "memory"); } while (0)

    #define CPB(kc, st) do { \
        const unsigned char* gsrc = g_WaImg + (size_t)((nblk * NC + (kc))) * BLK_BYTES + t * 16; \
        uint32_t sdst = sB + (st) * 16384 + t * 16; \
        cp16(sdst,          gsrc); \
        cp16(sdst + 4096,   gsrc + 4096); \
        cp16(sdst + 8192,   gsrc + 8192); \
        cp16(sdst + 12288,  gsrc + 12288); } while (0)

    LDA(0);
    CPB(0, 0); CP_COMMIT();
    CVTSTS(0, sA, 8192);

    for (int kc = 0; kc < NC; ++kc) {
        const int st = kc & 1;
        __syncthreads();
        if (kc + 1 < NC) {
            LDA(kc + 1);
            CPB(kc + 1, st ^ 1); CP_COMMIT();
            CP_WAIT(1);
        } else {
            CP_WAIT(0);
        }
        __syncthreads();

        const uint32_t aBase = sA + st * 16384;
        const uint32_t bBase = sB + st * 16384;
        #pragma unroll
        for (int ks = 0; ks < 2; ++ks) {
            uint32_t ah[2][4], al[2][4];
            #pragma unroll
            for (int mt = 0; mt < 2; ++mt) {
                const int m = wm + mt * 16 + laneMA;
                const int k8 = ks * 2 + laneK8A;
                const uint32_t off = (uint32_t)(m * 64 + ((k8 ^ ((m >> 1) & 3)) << 4));
                ldmx4(ah[mt], aBase + off);
                ldmx4(al[mt], aBase + 8192 + off);
            }
            #pragma unroll
            for (int nt = 0; nt < 4; ++nt) {
                uint32_t bh[4], bl[4];
                const int n = wn + nt * 16 + laneNB;
                const int k8 = ks * 2 + laneK8B;
                const uint32_t off = (uint32_t)(n * 64 + ((k8 ^ ((n >> 1) & 3)) << 4));
                ldmx4(bh, bBase + off);
                ldmx4(bl, bBase + 8192 + off);
                #pragma unroll
                for (int mt = 0; mt < 2; ++mt)
                    #pragma unroll
                    for (int half = 0; half < 2; ++half) {
                        float* a4 = acc[mt][nt * 2 + half];
                        mma_bf16(a4, ah[mt], &bh[half * 2]);
                        mma_bf16(a4, ah[mt], &bl[half * 2]);
                        mma_bf16(a4, al[mt], &bh[half * 2]);
                    }
            }
        }
        if (kc + 1 < NC) CVTSTS(st ^ 1, sA + (st ^ 1) * 16384, 8192);
    }

    const int n0 = nblk * 128;
    #pragma unroll
    for (int mt = 0; mt < 2; ++mt) {
        const int r0 = m0 + wm + mt * 16 + (lane >> 2);
        #pragma unroll
        for (int ng = 0; ng < 8; ++ng) {
            const int c = n0 + wn + ng * 8 + (lane & 3) * 2;
            const float b0 = bias[c], b1 = bias[c + 1];
            float2 v0 = { acc[mt][ng][0] + b0, acc[mt][ng][1] + b1 };
            float2 v1 = { acc[mt][ng][2] + b0, acc[mt][ng][3] + b1 };
            *(float2*)(g_h + (size_t)r0 * 256 + c)       = v0;
            *(float2*)(g_h + (size_t)(r0 + 8) * 256 + c) = v1;
        }
    }
}

// ------------------------- fused e-GEMM + attention + LayerNorm -------------------------
// CTA: M=96 rows (8 atoms), N=256 full width, 512 threads (16 warps, warp tile 48x32).
// e never touches DRAM: acc -> smem -> attention -> out.
#define FM 96
#define ESTR 260                    // s_e row stride in floats (bank-staggered)
#define FDYN_BYTES (FM * ESTR * 4 + 1024)   // >= staging (24576 + 65536 = 90112)? no: take max below

__global__ void __launch_bounds__(512, 1)
fused_e_attn(const float* __restrict__ nbr, const float* __restrict__ bnb,
             const float* __restrict__ smask, const float* __restrict__ amask,
             const float* __restrict__ wal, const float* __restrict__ bal,
             const float* __restrict__ gamma, const float* __restrict__ beta,
             float* __restrict__ out)
{
    extern __shared__ unsigned char sm[];
    __shared__ float s_red[16][2];

    const int t = threadIdx.x;
    const int lane = t & 31, wid = t >> 5;
    const int m0 = blockIdx.x * FM;

    const uint32_t sA = smem_u32(sm);            // A: 2 stages x (hi 6KB + lo 6KB) = 24KB
    const uint32_t sB = sA + 24576;              // B: 2 stages x (hi 16KB + lo 16KB) = 64KB
    float* s_e = (float*)sm;                     // epilogue overlay: 96 x 260 fp32

    const int wm = (wid & 1) * 48;               // 2 m-warps
    const int wn = (wid >> 1) * 32;              // 8 n-warps
    const int laneMA  = (lane & 7) + ((lane >> 3) & 1) * 8;
    const int laneK8A = lane >> 4;
    const int laneNB  = (lane & 7) + ((lane >> 4) & 1) * 8;
    const int laneK8B = (lane >> 3) & 1;

    float acc[3][4][4];
    #pragma unroll
    for (int mt = 0; mt < 3; ++mt)
        #pragma unroll
        for (int ng = 0; ng < 4; ++ng)
            #pragma unroll
            for (int j = 0; j < 4; ++j) acc[mt][ng][j] = 0.f;

    // A staging: threads t<192, 2 per row
    const int srow = t >> 1, shalf = t & 1;
    const bool stager = (t < 2 * FM);
    const float* Xrow = nbr + (size_t)(m0 + srow) * D_NBR + shalf * 16;
    const uint32_t offH0 = swz(srow, shalf * 16);
    const uint32_t offH1 = swz(srow, shalf * 16 + 8);

    float4 pf[4];
    #define FLDA(kc) do { if (stager) { \
        const float4* xp = (const float4*)(Xrow + (kc) * 32); \
        pf[0] = xp[0]; pf[1] = xp[1]; pf[2] = xp[2]; pf[3] = xp[3]; } } while (0)

    #define FCVTSTS(st) do { if (stager) { \
        uint32_t ab = sA + (st) * 12288; \
        uint4 hi0, lo0, hi1, lo1; \
        hi0.x = pack_bf2(pf[0].x, pf[0].y); hi0.y = pack_bf2(pf[0].z, pf[0].w); \
        hi0.z = pack_bf2(pf[1].x, pf[1].y); hi0.w = pack_bf2(pf[1].z, pf[1].w); \
        hi1.x = pack_bf2(pf[2].x, pf[2].y); hi1.y = pack_bf2(pf[2].z, pf[2].w); \
        hi1.z = pack_bf2(pf[3].x, pf[3].y); hi1.w = pack_bf2(pf[3].z, pf[3].w); \
        lo0.x = pack_bf2(pf[0].x - __bfloat162float(__float2bfloat16(pf[0].x)), \
                         pf[0].y - __bfloat162float(__float2bfloat16(pf[0].y))); \
        lo0.y = pack_bf2(pf[0].z - __bfloat162float(__float2bfloat16(pf[0].z)), \
                         pf[0].w - __bfloat162float(__float2bfloat16(pf[0].w))); \
        lo0.z = pack_bf2(pf[1].x - __bfloat162float(__float2bfloat16(pf[1].x)), \
                         pf[1].y - __bfloat162float(__float2bfloat16(pf[1].y))); \
        lo0.w = pack_bf2(pf[1].z - __bfloat162float(__float2bfloat16(pf[1].z)), \
                         pf[1].w - __bfloat162float(__float2bfloat16(pf[1].w))); \
        lo1.x = pack_bf2(pf[2].x - __bfloat162float(__float2bfloat16(pf[2].x)), \
                         pf[2].y - __bfloat162float(__float2bfloat16(pf[2].y))); \
        lo1.y = pack_bf2(pf[2].z - __bfloat162float(__float2bfloat16(pf[2].z)), \
                         pf[2].w - __bfloat162float(__float2bfloat16(pf[2].w))); \
        lo1.z = pack_bf2(pf[3].x - __bfloat162float(__float2bfloat16(pf[3].x)), \
                         pf[3].y - __bfloat162float(__float2bfloat16(pf[3].y))); \
        lo1.w = pack_bf2(pf[3].z - __bfloat162float(__float2bfloat16(pf[3].z)), \
                         pf[3].w - __bfloat162float(__float2bfloat16(pf[3].w))); \
        asm volatile("st.shared.v4.b32 [%0], {%1,%2,%3,%4};" :: "r"(ab + offH0), \
            "r"(hi0.x), "r"(hi0.y), "r"(hi0.z), "r"(hi0.w) : "memory"); \
        asm volatile("st.shared.v4.b32 [%0], {%1,%2,%3,%4};" :: "r"(ab + offH1), \
            "r"(hi1.x), "r"(hi1.y), "r"(hi1.z), "r"(hi1.w) : "memory"); \
        asm volatile("st.shared.v4.b32 [%0], {%1,%2,%3,%4};" :: "r"(ab + 6144 + offH0), \
            "r"(lo0.x), "r"(lo0.y), "r"(lo0.z), "r"(lo0.w) : "memory"); \
        asm volatile("st.shared.v4.b32 [%0], {%1,%2,%3,%4};" :: "r"(ab + 6144 + offH1), \
            "r"(lo1.x), "r"(lo1.y), "r"(lo1.z), "r"(lo1.w) : "memory"); } } while (0)

    #define FCPB(kc, st) do { \
        const unsigned char* gsrc = g_WnImg + (size_t)(kc) * WNC_BYTES + t * 16; \
        uint32_t sdst = sB + (st) * 32768 + t * 16; \
        cp16(sdst,           gsrc); \
        cp16(sdst + 8192,    gsrc + 8192); \
        cp16(sdst + 16384,   gsrc + 16384); \
        cp16(sdst + 24576,   gsrc + 24576); } while (0)

    FLDA(0);
    FCPB(0, 0); CP_COMMIT();
    FCVTSTS(0);

    for (int kc = 0; kc < NC_E; ++kc) {
        const int st = kc & 1;
        __syncthreads();                  // stage st^1 readers done
        if (kc + 1 < NC_E) {
            FLDA(kc + 1);
            FCPB(kc + 1, st ^ 1); CP_COMMIT();
            CP_WAIT(1);
        } else {
            CP_WAIT(0);
        }
        __syncthreads();                  // stage st visible

        const uint32_t aBase = sA + st * 12288;
        const uint32_t bBase = sB + st * 32768;
        #pragma unroll
        for (int ks = 0; ks < 2; ++ks) {
            uint32_t ah[3][4], al[3][4];
            #pragma unroll
            for (int mt = 0; mt < 3; ++mt) {
                const int m = wm + mt * 16 + laneMA;
                const int k8 = ks * 2 + laneK8A;
                const uint32_t off = (uint32_t)(m * 64 + ((k8 ^ ((m >> 1) & 3)) << 4));
                ldmx4(ah[mt], aBase + off);
                ldmx4(al[mt], aBase + 6144 + off);
            }
            #pragma unroll
            for (int nt = 0; nt < 2; ++nt) {
                uint32_t bh[4], bl[4];
                const int n = wn + nt * 16 + laneNB;
                const int k8 = ks * 2 + laneK8B;
                const uint32_t off = (uint32_t)(n * 64 + ((k8 ^ ((n >> 1) & 3)) << 4));
                ldmx4(bh, bBase + off);
                ldmx4(bl, bBase + 16384 + off);
                #pragma unroll
                for (int mt = 0; mt < 3; ++mt)
                    #pragma unroll
                    for (int half = 0; half < 2; ++half) {
                        float* a4 = acc[mt][nt * 2 + half];
                        mma_bf16(a4, ah[mt], &bh[half * 2]);
                        mma_bf16(a4, ah[mt], &bl[half * 2]);
                        mma_bf16(a4, al[mt], &bh[half * 2]);
                    }
            }
        }
        if (kc + 1 < NC_E) FCVTSTS(st ^ 1);
    }

    // ---- epilogue 1: acc + bias -> smem e tile ----
    __syncthreads();                      // all ldmatrix reads done; s_e overlays stages
    #pragma unroll
    for (int mt = 0; mt < 3; ++mt) {
        const int r0 = wm + mt * 16 + (lane >> 2);
        #pragma unroll
        for (int ng = 0; ng < 4; ++ng) {
            const int c = wn + ng * 8 + (lane & 3) * 2;
            const float b0 = __ldg(bnb + c), b1 = __ldg(bnb + c + 1);
            float2 v0 = { acc[mt][ng][0] + b0, acc[mt][ng][1] + b1 };
            float2 v1 = { acc[mt][ng][2] + b0, acc[mt][ng][3] + b1 };
            *(float2*)(s_e + (size_t)r0 * ESTR + c)       = v0;
            *(float2*)(s_e + (size_t)(r0 + 8) * ESTR + c) = v1;
        }
    }
    __syncthreads();

    // ---- epilogue 2: attention + softmax + ctx + LayerNorm (8 atoms x 64 threads) ----
    {
        const int g  = t >> 6;            // atom in CTA (0..7)
        const int tx = t & 63;
        const int bn = blockIdx.x * 8 + g;

        const float4 h4 = *(const float4*)(g_h + (size_t)bn * 256 + tx * 4);
        const float4 w4 = *(const float4*)(wal + ((tx * 4) & 31));
        float4 e4[KQ];
        #pragma unroll
        for (int k = 0; k < KQ; ++k)
            e4[k] = *(const float4*)(s_e + (size_t)(g * KQ + k) * ESTR + tx * 4);
        const float bal0 = __ldg(bal);

        float sc[KQ];
        #pragma unroll
        for (int k = 0; k < KQ; ++k) {
            float x, s = 0.f;
            x = h4.x + e4[k].x; x = fmaxf(x, 0.01f * x); s = fmaf(x, w4.x, s);
            x = h4.y + e4[k].y; x = fmaxf(x, 0.01f * x); s = fmaf(x, w4.y, s);
            x = h4.z + e4[k].z; x = fmaxf(x, 0.01f * x); s = fmaf(x, w4.z, s);
            x = h4.w + e4[k].w; x = fmaxf(x, 0.01f * x); s = fmaf(x, w4.w, s);
            sc[k] = s;
        }
        #pragma unroll
        for (int o = 1; o < 8; o <<= 1)
            #pragma unroll
            for (int k = 0; k < KQ; ++k)
                sc[k] += __shfl_xor_sync(0xffffffffu, sc[k], o);

        float mx = -3.4e38f;
        #pragma unroll
        for (int k = 0; k < KQ; ++k) {
            sc[k] += bal0 + __ldg(smask + bn * KQ + k);
            mx = fmaxf(mx, sc[k]);
        }
        float sum = 0.f;
        #pragma unroll
        for (int k = 0; k < KQ; ++k) { sc[k] = __expf(sc[k] - mx); sum += sc[k]; }
        const float inv = 1.f / sum;
        #pragma unroll
        for (int k = 0; k < KQ; ++k) sc[k] = sc[k] * inv * __ldg(amask + bn * KQ + k);

        float c0 = 0.f, c1 = 0.f, c2 = 0.f, c3 = 0.f;
        #pragma unroll
        for (int k = 0; k < KQ; ++k) {
            c0 = fmaf(sc[k], e4[k].x, c0);
            c1 = fmaf(sc[k], e4[k].y, c1);
            c2 = fmaf(sc[k], e4[k].z, c2);
            c3 = fmaf(sc[k], e4[k].w, c3);
        }

        float v  = c0 + c1 + c2 + c3;
        float v2 = c0 * c0 + c1 * c1 + c2 * c2 + c3 * c3;
        #pragma unroll
        for (int o = 16; o > 0; o >>= 1) {
            v  += __shfl_xor_sync(0xffffffffu, v, o);
            v2 += __shfl_xor_sync(0xffffffffu, v2, o);
        }
        if ((t & 31) == 0) { s_red[wid][0] = v; s_red[wid][1] = v2; }
        __syncthreads();
        const float s  = s_red[g * 2][0] + s_red[g * 2 + 1][0];
        const float s2 = s_red[g * 2][1] + s_red[g * 2 + 1][1];
        const float mu  = s * (1.f / D_NEW);
        const float var = s2 * (1.f / D_NEW) - mu * mu;
        const float rinv = rsqrtf(var + LN_EPS);

        const float4 gv = *(const float4*)(gamma + tx * 4);
        const float4 bv = *(const float4*)(beta + tx * 4);
        float4 o;
        o.x = (c0 - mu) * rinv * gv.x + bv.x;
        o.y = (c1 - mu) * rinv * gv.y + bv.y;
        o.z = (c2 - mu) * rinv * gv.z + bv.z;
        o.w = (c3 - mu) * rinv * gv.w + bv.w;
        *(float4*)(out + (size_t)bn * D_NEW + tx * 4) = o;
    }
    #undef FLDA
    #undef FCVTSTS
    #undef FCPB
}

// ------------------------- launch -------------------------
#define GEMM_DYN_BYTES 65536
#define FUSED_DYN_BYTES (FM * ESTR * 4 > 90112 ? FM * ESTR * 4 : 90112)   // max(99840, 90112)

extern "C" void kernel_launch(void* const* d_in, const int* in_sizes, int n_in,
                              void* d_out, int out_size)
{
    (void)in_sizes; (void)n_in; (void)out_size;
    const float* atom   = (const float*)d_in[0];
    const float* nbr    = (const float*)d_in[1];
    const float* smask  = (const float*)d_in[2];
    const float* amask  = (const float*)d_in[3];
    const float* Wa     = (const float*)d_in[4];
    const float* ba     = (const float*)d_in[5];
    const float* Wn     = (const float*)d_in[6];
    const float* bnb    = (const float*)d_in[7];
    const float* wal    = (const float*)d_in[8];
    const float* bal    = (const float*)d_in[9];
    const float* gamma  = (const float*)d_in[10];
    const float* beta   = (const float*)d_in[11];
    float* out = (float*)d_out;

    cudaFuncSetAttribute(gemm_h, cudaFuncAttributeMaxDynamicSharedMemorySize, GEMM_DYN_BYTES);
    cudaFuncSetAttribute(fused_e_attn, cudaFuncAttributeMaxDynamicSharedMemorySize, FUSED_DYN_BYTES);

    prep_w<<<((D_NBR + D_NEW) * 256 + 255) / 256, 256>>>(Wn, Wa);
    gemm_h<<<dim3(BN_TOT / 128, 2), 256, GEMM_DYN_BYTES>>>(atom, ba);
    fused_e_attn<<<M_E / FM, 512, FUSED_DYN_BYTES>>>(nbr, bnb, smask, amask,
                                                     wal, bal, gamma, beta, out);
}

// round 11
// speedup vs baseline: 1.0649x; 1.0649x over previous
#include <cuda_runtime.h>
#include <cuda_bf16.h>
#include <cstdint>

#define KQ     12
#define D_NBR  320
#define D_NEW  256
#define HQ     8
#define DKQ    32
#define LN_EPS 1e-5f
#define BN_TOT (64 * 128)          // 8192 atoms
#define M_E    (BN_TOT * KQ)       // 98304 neighbor rows
#define NC_E   (D_NBR / 32)        // 10 k-chunks (BK=32)
#define NC_H   (D_NEW / 32)        // 8 k-chunks
#define BLK_BYTES 16384            // Wa: one (128n x 32k) hi+lo image block
#define WNC_BYTES 32768            // Wn: one (256n x 32k) hi+lo image block

// ------------------------- device scratch -------------------------
__device__ __align__(16) unsigned char g_WnImg[NC_E * WNC_BYTES];          // 320 KB
__device__ __align__(16) unsigned char g_WaImg[2 * NC_H * BLK_BYTES];      // 256 KB
__device__ float g_h[(size_t)BN_TOT * 256];
__device__ float g_part[BN_TOT][2][2];     // per atom, per n-half: (sum, sumsq)

// ------------------------- helpers -------------------------
__device__ __forceinline__ uint32_t smem_u32(const void* p) {
    uint32_t a;
    asm("{ .reg .u64 t; cvta.to.shared.u64 t, %1; cvt.u32.u64 %0, t; }" : "=r"(a) : "l"(p));
    return a;
}
__device__ __forceinline__ void ldmx4(uint32_t* r, uint32_t addr) {
    asm volatile("ldmatrix.sync.aligned.m8n8.x4.shared.b16 {%0,%1,%2,%3}, [%4];"
        : "=r"(r[0]), "=r"(r[1]), "=r"(r[2]), "=r"(r[3]) : "r"(addr));
}
__device__ __forceinline__ void mma_bf16(float* d, const uint32_t* a, const uint32_t* b) {
    asm volatile(
        "mma.sync.aligned.m16n8k16.row.col.f32.bf16.bf16.f32 "
        "{%0,%1,%2,%3}, {%4,%5,%6,%7}, {%8,%9}, {%0,%1,%2,%3};"
        : "+f"(d[0]), "+f"(d[1]), "+f"(d[2]), "+f"(d[3])
        : "r"(a[0]), "r"(a[1]), "r"(a[2]), "r"(a[3]), "r"(b[0]), "r"(b[1]));
}
__device__ __forceinline__ void cp16(uint32_t saddr, const void* g) {
    asm volatile("cp.async.cg.shared.global [%0], [%1], 16;" :: "r"(saddr), "l"(g) : "memory");
}
#define CP_COMMIT() asm volatile("cp.async.commit_group;" ::: "memory")
#define CP_WAIT(n)  asm volatile("cp.async.wait_group %0;" :: "n"(n) : "memory")

// swizzled offset inside an (R rows x 32k) bf16 image (row-major rows of 64B)
__device__ __host__ __forceinline__ uint32_t swz(int r, int k) {
    return (uint32_t)(r * 64 + ((((k >> 3) ^ ((r >> 1) & 3))) << 4) + (k & 7) * 2);
}
__device__ __forceinline__ uint32_t pack_bf2(float a, float b) {
    __nv_bfloat162 p = __floats2bfloat162_rn(a, b);
    return *(uint32_t*)&p;
}

// ------------------------- prep: split W into bf16 hi/lo swizzled images -------------------------
__global__ void prep_w(const float* __restrict__ Wn, const float* __restrict__ Wa) {
    int i = blockIdx.x * blockDim.x + threadIdx.x;
    if (i < D_NBR * 256) {
        const int k = i >> 8, n = i & 255;
        const int kc = k >> 5, kl = k & 31;
        const float x = Wn[k * 256 + n];
        const __nv_bfloat16 hi = __float2bfloat16(x);
        const __nv_bfloat16 lo = __float2bfloat16(x - __bfloat162float(hi));
        unsigned char* base = g_WnImg + (size_t)kc * WNC_BYTES;
        const uint32_t off = swz(n, kl);
        *(__nv_bfloat16*)(base + off)         = hi;
        *(__nv_bfloat16*)(base + 16384 + off) = lo;
    } else if (i < (D_NBR + D_NEW) * 256) {
        const int idx = i - D_NBR * 256;
        const int k = idx >> 8, n = idx & 255;
        const int ntile = n >> 7, nl = n & 127, kc = k >> 5, kl = k & 31;
        const float x = Wa[k * 256 + n];
        const __nv_bfloat16 hi = __float2bfloat16(x);
        const __nv_bfloat16 lo = __float2bfloat16(x - __bfloat162float(hi));
        unsigned char* base = g_WaImg + (size_t)(ntile * NC_H + kc) * BLK_BYTES;
        const uint32_t off = swz(nl, kl);
        *(__nv_bfloat16*)(base + off)        = hi;
        *(__nv_bfloat16*)(base + 8192 + off) = lo;
    }
}

// ------------------------- h-GEMM (bf16x3 mma): g_h = atom @ Wa + ba -------------------------
__global__ void __launch_bounds__(256, 2)
gemm_h(const float* __restrict__ X, const float* __restrict__ bias)
{
    extern __shared__ unsigned char sm[];
    const int t = threadIdx.x;
    const int lane = t & 31, wid = t >> 5;
    const int m0 = blockIdx.x * 128;
    const int nblk = blockIdx.y;
    const int K = D_NEW, NC = NC_H;

    const uint32_t sA = smem_u32(sm);
    const uint32_t sB = sA + 32768;

    const int wm = (wid & 3) * 32;
    const int wn = (wid >> 2) * 64;
    const int laneMA  = (lane & 7) + ((lane >> 3) & 1) * 8;
    const int laneK8A = lane >> 4;
    const int laneNB  = (lane & 7) + ((lane >> 4) & 1) * 8;
    const int laneK8B = (lane >> 3) & 1;

    float acc[2][8][4];
    #pragma unroll
    for (int mt = 0; mt < 2; ++mt)
        #pragma unroll
        for (int ng = 0; ng < 8; ++ng)
            #pragma unroll
            for (int j = 0; j < 4; ++j) acc[mt][ng][j] = 0.f;

    const int srow = t >> 1, shalf = t & 1;
    const float* Xrow = X + (size_t)(m0 + srow) * K + shalf * 16;
    const uint32_t offH0 = swz(srow, shalf * 16);
    const uint32_t offH1 = swz(srow, shalf * 16 + 8);

    float4 pf[4];
    #define LDA(kc) do { \
        const float4* xp = (const float4*)(Xrow + (kc) * 32); \
        pf[0] = xp[0]; pf[1] = xp[1]; pf[2] = xp[2]; pf[3] = xp[3]; } while (0)

    #define CVTSTS(ab, lodelta) do { \
        uint4 hi0, lo0, hi1, lo1; \
        hi0.x = pack_bf2(pf[0].x, pf[0].y); hi0.y = pack_bf2(pf[0].z, pf[0].w); \
        hi0.z = pack_bf2(pf[1].x, pf[1].y); hi0.w = pack_bf2(pf[1].z, pf[1].w); \
        hi1.x = pack_bf2(pf[2].x, pf[2].y); hi1.y = pack_bf2(pf[2].z, pf[2].w); \
        hi1.z = pack_bf2(pf[3].x, pf[3].y); hi1.w = pack_bf2(pf[3].z, pf[3].w); \
        lo0.x = pack_bf2(pf[0].x - __bfloat162float(__float2bfloat16(pf[0].x)), \
                         pf[0].y - __bfloat162float(__float2bfloat16(pf[0].y))); \
        lo0.y = pack_bf2(pf[0].z - __bfloat162float(__float2bfloat16(pf[0].z)), \
                         pf[0].w - __bfloat162float(__float2bfloat16(pf[0].w))); \
        lo0.z = pack_bf2(pf[1].x - __bfloat162float(__float2bfloat16(pf[1].x)), \
                         pf[1].y - __bfloat162float(__float2bfloat16(pf[1].y))); \
        lo0.w = pack_bf2(pf[1].z - __bfloat162float(__float2bfloat16(pf[1].z)), \
                         pf[1].w - __bfloat162float(__float2bfloat16(pf[1].w))); \
        lo1.x = pack_bf2(pf[2].x - __bfloat162float(__float2bfloat16(pf[2].x)), \
                         pf[2].y - __bfloat162float(__float2bfloat16(pf[2].y))); \
        lo1.y = pack_bf2(pf[2].z - __bfloat162float(__float2bfloat16(pf[2].z)), \
                         pf[2].w - __bfloat162float(__float2bfloat16(pf[2].w))); \
        lo1.z = pack_bf2(pf[3].x - __bfloat162float(__float2bfloat16(pf[3].x)), \
                         pf[3].y - __bfloat162float(__float2bfloat16(pf[3].y))); \
        lo1.w = pack_bf2(pf[3].z - __bfloat162float(__float2bfloat16(pf[3].z)), \
                         pf[3].w - __bfloat162float(__float2bfloat16(pf[3].w))); \
        asm volatile("st.shared.v4.b32 [%0], {%1,%2,%3,%4};" :: "r"((ab) + offH0), \
            "r"(hi0.x), "r"(hi0.y), "r"(hi0.z), "r"(hi0.w) : "memory"); \
        asm volatile("st.shared.v4.b32 [%0], {%1,%2,%3,%4};" :: "r"((ab) + offH1), \
            "r"(hi1.x), "r"(hi1.y), "r"(hi1.z), "r"(hi1.w) : "memory"); \
        asm volatile("st.shared.v4.b32 [%0], {%1,%2,%3,%4};" :: "r"((ab) + (lodelta) + offH0), \
            "r"(lo0.x), "r"(lo0.y), "r"(lo0.z), "r"(lo0.w) : "memory"); \
        asm volatile("st.shared.v4.b32 [%0], {%1,%2,%3,%4};" :: "r"((ab) + (lodelta) + offH1), \
            "r"(lo1.x), "r"(lo1.y), "r"(lo1.z), "r"(lo1.w) : "memory"); } while (0)

    #define CPB(kc, st) do { \
        const unsigned char* gsrc = g_WaImg + (size_t)((nblk * NC + (kc))) * BLK_BYTES + t * 16; \
        uint32_t sdst = sB + (st) * 16384 + t * 16; \
        cp16(sdst,          gsrc); \
        cp16(sdst + 4096,   gsrc + 4096); \
        cp16(sdst + 8192,   gsrc + 8192); \
        cp16(sdst + 12288,  gsrc + 12288); } while (0)

    LDA(0);
    CPB(0, 0); CP_COMMIT();
    CVTSTS(sA, 8192);

    for (int kc = 0; kc < NC; ++kc) {
        const int st = kc & 1;
        __syncthreads();
        if (kc + 1 < NC) {
            LDA(kc + 1);
            CPB(kc + 1, st ^ 1); CP_COMMIT();
            CP_WAIT(1);
        } else {
            CP_WAIT(0);
        }
        __syncthreads();

        const uint32_t aBase = sA + st * 16384;
        const uint32_t bBase = sB + st * 16384;
        #pragma unroll
        for (int ks = 0; ks < 2; ++ks) {
            uint32_t ah[2][4], al[2][4];
            #pragma unroll
            for (int mt = 0; mt < 2; ++mt) {
                const int m = wm + mt * 16 + laneMA;
                const int k8 = ks * 2 + laneK8A;
                const uint32_t off = (uint32_t)(m * 64 + ((k8 ^ ((m >> 1) & 3)) << 4));
                ldmx4(ah[mt], aBase + off);
                ldmx4(al[mt], aBase + 8192 + off);
            }
            #pragma unroll
            for (int nt = 0; nt < 4; ++nt) {
                uint32_t bh[4], bl[4];
                const int n = wn + nt * 16 + laneNB;
                const int k8 = ks * 2 + laneK8B;
                const uint32_t off = (uint32_t)(n * 64 + ((k8 ^ ((n >> 1) & 3)) << 4));
                ldmx4(bh, bBase + off);
                ldmx4(bl, bBase + 8192 + off);
                #pragma unroll
                for (int mt = 0; mt < 2; ++mt)
                    #pragma unroll
                    for (int half = 0; half < 2; ++half) {
                        float* a4 = acc[mt][nt * 2 + half];
                        mma_bf16(a4, ah[mt], &bh[half * 2]);
                        mma_bf16(a4, ah[mt], &bl[half * 2]);
                        mma_bf16(a4, al[mt], &bh[half * 2]);
                    }
            }
        }
        if (kc + 1 < NC) CVTSTS(sA + (st ^ 1) * 16384, 8192);
    }

    const int n0 = nblk * 128;
    #pragma unroll
    for (int mt = 0; mt < 2; ++mt) {
        const int r0 = m0 + wm + mt * 16 + (lane >> 2);
        #pragma unroll
        for (int ng = 0; ng < 8; ++ng) {
            const int c = n0 + wn + ng * 8 + (lane & 3) * 2;
            const float b0 = bias[c], b1 = bias[c + 1];
            float2 v0 = { acc[mt][ng][0] + b0, acc[mt][ng][1] + b1 };
            float2 v1 = { acc[mt][ng][2] + b0, acc[mt][ng][3] + b1 };
            *(float2*)(g_h + (size_t)r0 * 256 + c)       = v0;
            *(float2*)(g_h + (size_t)(r0 + 8) * 256 + c) = v1;
        }
    }
    #undef LDA
    #undef CVTSTS
    #undef CPB
}

// ------------------------- fused e-GEMM + attention (N=128 half) -------------------------
// CTA: M=96 rows (8 atoms) x N=128 (4 heads), 256 threads (8 warps, warp tile 48x32).
// bid = mtile*2 + nblk  (halves adjacent -> co-scheduled -> nbr L2 reuse).
// Writes ctx half to out + per-atom (sum,sumsq) partials; LN finished by ln_final.
#define FM 96
#define ESTR 132
#define FDYN_BYTES 57344           // A 2x12KB + B 2x16KB; e tile 96*132*4 = 50688 overlay

__global__ void __launch_bounds__(256, 2)
fused_e_attn(const float* __restrict__ nbr, const float* __restrict__ bnb,
             const float* __restrict__ smask, const float* __restrict__ amask,
             const float* __restrict__ wal, const float* __restrict__ bal,
             float* __restrict__ out)
{
    extern __shared__ unsigned char sm[];

    const int t = threadIdx.x;
    const int lane = t & 31, wid = t >> 5;
    const int bid = blockIdx.x;
    const int nblk = bid & 1;
    const int m0 = (bid >> 1) * FM;

    const uint32_t sA = smem_u32(sm);            // A: 2 stages x (hi 6KB + lo 6KB) = 24KB
    const uint32_t sB = sA + 24576;              // B: 2 stages x (hi 8KB + lo 8KB) = 32KB
    float* s_e = (float*)sm;                     // epilogue overlay: 96 x 132 fp32

    const int wm = (wid & 1) * 48;               // 2 m-warps
    const int wn = (wid >> 1) * 32;              // 4 n-warps
    const int laneMA  = (lane & 7) + ((lane >> 3) & 1) * 8;
    const int laneK8A = lane >> 4;
    const int laneNB  = (lane & 7) + ((lane >> 4) & 1) * 8;
    const int laneK8B = (lane >> 3) & 1;

    float acc[3][4][4];
    #pragma unroll
    for (int mt = 0; mt < 3; ++mt)
        #pragma unroll
        for (int ng = 0; ng < 4; ++ng)
            #pragma unroll
            for (int j = 0; j < 4; ++j) acc[mt][ng][j] = 0.f;

    // A staging: threads t<192, 2 per row
    const int srow = t >> 1, shalf = t & 1;
    const bool stager = (t < 2 * FM);
    const float* Xrow = nbr + (size_t)(m0 + srow) * D_NBR + shalf * 16;
    const uint32_t offH0 = swz(srow, shalf * 16);
    const uint32_t offH1 = swz(srow, shalf * 16 + 8);

    float4 pf[4];
    #define FLDA(kc) do { if (stager) { \
        const float4* xp = (const float4*)(Xrow + (kc) * 32); \
        pf[0] = xp[0]; pf[1] = xp[1]; pf[2] = xp[2]; pf[3] = xp[3]; } } while (0)

    #define FCVTSTS(st) do { if (stager) { \
        uint32_t ab = sA + (st) * 12288; \
        uint4 hi0, lo0, hi1, lo1; \
        hi0.x = pack_bf2(pf[0].x, pf[0].y); hi0.y = pack_bf2(pf[0].z, pf[0].w); \
        hi0.z = pack_bf2(pf[1].x, pf[1].y); hi0.w = pack_bf2(pf[1].z, pf[1].w); \
        hi1.x = pack_bf2(pf[2].x, pf[2].y); hi1.y = pack_bf2(pf[2].z, pf[2].w); \
        hi1.z = pack_bf2(pf[3].x, pf[3].y); hi1.w = pack_bf2(pf[3].z, pf[3].w); \
        lo0.x = pack_bf2(pf[0].x - __bfloat162float(__float2bfloat16(pf[0].x)), \
                         pf[0].y - __bfloat162float(__float2bfloat16(pf[0].y))); \
        lo0.y = pack_bf2(pf[0].z - __bfloat162float(__float2bfloat16(pf[0].z)), \
                         pf[0].w - __bfloat162float(__float2bfloat16(pf[0].w))); \
        lo0.z = pack_bf2(pf[1].x - __bfloat162float(__float2bfloat16(pf[1].x)), \
                         pf[1].y - __bfloat162float(__float2bfloat16(pf[1].y))); \
        lo0.w = pack_bf2(pf[1].z - __bfloat162float(__float2bfloat16(pf[1].z)), \
                         pf[1].w - __bfloat162float(__float2bfloat16(pf[1].w))); \
        lo1.x = pack_bf2(pf[2].x - __bfloat162float(__float2bfloat16(pf[2].x)), \
                         pf[2].y - __bfloat162float(__float2bfloat16(pf[2].y))); \
        lo1.y = pack_bf2(pf[2].z - __bfloat162float(__float2bfloat16(pf[2].z)), \
                         pf[2].w - __bfloat162float(__float2bfloat16(pf[2].w))); \
        lo1.z = pack_bf2(pf[3].x - __bfloat162float(__float2bfloat16(pf[3].x)), \
                         pf[3].y - __bfloat162float(__float2bfloat16(pf[3].y))); \
        lo1.w = pack_bf2(pf[3].z - __bfloat162float(__float2bfloat16(pf[3].z)), \
                         pf[3].w - __bfloat162float(__float2bfloat16(pf[3].w))); \
        asm volatile("st.shared.v4.b32 [%0], {%1,%2,%3,%4};" :: "r"(ab + offH0), \
            "r"(hi0.x), "r"(hi0.y), "r"(hi0.z), "r"(hi0.w) : "memory"); \
        asm volatile("st.shared.v4.b32 [%0], {%1,%2,%3,%4};" :: "r"(ab + offH1), \
            "r"(hi1.x), "r"(hi1.y), "r"(hi1.z), "r"(hi1.w) : "memory"); \
        asm volatile("st.shared.v4.b32 [%0], {%1,%2,%3,%4};" :: "r"(ab + 6144 + offH0), \
            "r"(lo0.x), "r"(lo0.y), "r"(lo0.z), "r"(lo0.w) : "memory"); \
        asm volatile("st.shared.v4.b32 [%0], {%1,%2,%3,%4};" :: "r"(ab + 6144 + offH1), \
            "r"(lo1.x), "r"(lo1.y), "r"(lo1.z), "r"(lo1.w) : "memory"); } } while (0)

    // B: this CTA's 128-row slice of the 256-row image (rows are 64B, slice contiguous)
    #define FCPB(kc, st) do { \
        const unsigned char* hsrc = g_WnImg + (size_t)(kc) * WNC_BYTES + nblk * 8192 + t * 16; \
        const unsigned char* lsrc = hsrc + 16384; \
        uint32_t sdst = sB + (st) * 16384 + t * 16; \
        cp16(sdst,          hsrc); \
        cp16(sdst + 4096,   hsrc + 4096); \
        cp16(sdst + 8192,   lsrc); \
        cp16(sdst + 12288,  lsrc + 4096); } while (0)

    FLDA(0);
    FCPB(0, 0); CP_COMMIT();
    FCVTSTS(0);

    for (int kc = 0; kc < NC_E; ++kc) {
        const int st = kc & 1;
        __syncthreads();                  // stage st^1 readers done
        if (kc + 1 < NC_E) {
            FLDA(kc + 1);
            FCPB(kc + 1, st ^ 1); CP_COMMIT();
            CP_WAIT(1);
        } else {
            CP_WAIT(0);
        }
        __syncthreads();                  // stage st visible

        const uint32_t aBase = sA + st * 12288;
        const uint32_t bBase = sB + st * 16384;
        #pragma unroll
        for (int ks = 0; ks < 2; ++ks) {
            uint32_t ah[3][4], al[3][4];
            #pragma unroll
            for (int mt = 0; mt < 3; ++mt) {
                const int m = wm + mt * 16 + laneMA;
                const int k8 = ks * 2 + laneK8A;
                const uint32_t off = (uint32_t)(m * 64 + ((k8 ^ ((m >> 1) & 3)) << 4));
                ldmx4(ah[mt], aBase + off);
                ldmx4(al[mt], aBase + 6144 + off);
            }
            #pragma unroll
            for (int nt = 0; nt < 2; ++nt) {
                uint32_t bh[4], bl[4];
                const int n = wn + nt * 16 + laneNB;
                const int k8 = ks * 2 + laneK8B;
                const uint32_t off = (uint32_t)(n * 64 + ((k8 ^ ((n >> 1) & 3)) << 4));
                ldmx4(bh, bBase + off);
                ldmx4(bl, bBase + 8192 + off);
                #pragma unroll
                for (int mt = 0; mt < 3; ++mt)
                    #pragma unroll
                    for (int half = 0; half < 2; ++half) {
                        float* a4 = acc[mt][nt * 2 + half];
                        mma_bf16(a4, ah[mt], &bh[half * 2]);
                        mma_bf16(a4, ah[mt], &bl[half * 2]);
                        mma_bf16(a4, al[mt], &bh[half * 2]);
                    }
            }
        }
        if (kc + 1 < NC_E) FCVTSTS(st ^ 1);
    }

    // ---- epilogue 1: acc + bias -> smem e tile (96 x 128, local cols) ----
    __syncthreads();                      // all ldmatrix reads done; s_e overlays stages
    #pragma unroll
    for (int mt = 0; mt < 3; ++mt) {
        const int r0 = wm + mt * 16 + (lane >> 2);
        #pragma unroll
        for (int ng = 0; ng < 4; ++ng) {
            const int c = wn + ng * 8 + (lane & 3) * 2;     // local col 0..127
            const int cg = nblk * 128 + c;                  // global col
            const float b0 = __ldg(bnb + cg), b1 = __ldg(bnb + cg + 1);
            float2 v0 = { acc[mt][ng][0] + b0, acc[mt][ng][1] + b1 };
            float2 v1 = { acc[mt][ng][2] + b0, acc[mt][ng][3] + b1 };
            *(float2*)(s_e + (size_t)r0 * ESTR + c)       = v0;
            *(float2*)(s_e + (size_t)(r0 + 8) * ESTR + c) = v1;
        }
    }
    __syncthreads();

    // ---- epilogue 2: attention + softmax + ctx; warp = atom (32 threads x 4 cols = 128) ----
    {
        const int g  = wid;                // atom in CTA (0..7), one warp each
        const int bn = (bid >> 1) * 8 + g;
        const int colg = nblk * 128 + lane * 4;

        const float4 h4 = *(const float4*)(g_h + (size_t)bn * 256 + colg);
        const float4 w4 = *(const float4*)(wal + ((lane * 4) & 31));
        float4 e4[KQ];
        #pragma unroll
        for (int k = 0; k < KQ; ++k)
            e4[k] = *(const float4*)(s_e + (size_t)(g * KQ + k) * ESTR + lane * 4);
        const float bal0 = __ldg(bal);

        float sc[KQ];
        #pragma unroll
        for (int k = 0; k < KQ; ++k) {
            float x, s = 0.f;
            x = h4.x + e4[k].x; x = fmaxf(x, 0.01f * x); s = fmaf(x, w4.x, s);
            x = h4.y + e4[k].y; x = fmaxf(x, 0.01f * x); s = fmaf(x, w4.y, s);
            x = h4.z + e4[k].z; x = fmaxf(x, 0.01f * x); s = fmaf(x, w4.z, s);
            x = h4.w + e4[k].w; x = fmaxf(x, 0.01f * x); s = fmaf(x, w4.w, s);
            sc[k] = s;
        }
        #pragma unroll
        for (int o = 1; o < 8; o <<= 1)
            #pragma unroll
            for (int k = 0; k < KQ; ++k)
                sc[k] += __shfl_xor_sync(0xffffffffu, sc[k], o);

        float mx = -3.4e38f;
        #pragma unroll
        for (int k = 0; k < KQ; ++k) {
            sc[k] += bal0 + __ldg(smask + bn * KQ + k);
            mx = fmaxf(mx, sc[k]);
        }
        float sum = 0.f;
        #pragma unroll
        for (int k = 0; k < KQ; ++k) { sc[k] = __expf(sc[k] - mx); sum += sc[k]; }
        const float inv = 1.f / sum;
        #pragma unroll
        for (int k = 0; k < KQ; ++k) sc[k] = sc[k] * inv * __ldg(amask + bn * KQ + k);

        float c0 = 0.f, c1 = 0.f, c2 = 0.f, c3 = 0.f;
        #pragma unroll
        for (int k = 0; k < KQ; ++k) {
            c0 = fmaf(sc[k], e4[k].x, c0);
            c1 = fmaf(sc[k], e4[k].y, c1);
            c2 = fmaf(sc[k], e4[k].z, c2);
            c3 = fmaf(sc[k], e4[k].w, c3);
        }

        // LN partials over this 128-col half (full warp reduce)
        float v  = c0 + c1 + c2 + c3;
        float v2 = c0 * c0 + c1 * c1 + c2 * c2 + c3 * c3;
        #pragma unroll
        for (int o = 16; o > 0; o >>= 1) {
            v  += __shfl_xor_sync(0xffffffffu, v, o);
            v2 += __shfl_xor_sync(0xffffffffu, v2, o);
        }
        if (lane == 0) { g_part[bn][nblk][0] = v; g_part[bn][nblk][1] = v2; }

        float4 o;
        o.x = c0; o.y = c1; o.z = c2; o.w = c3;
        *(float4*)(out + (size_t)bn * D_NEW + colg) = o;
    }
    #undef FLDA
    #undef FCVTSTS
    #undef FCPB
}

// ------------------------- LN finish: normalize out in place -------------------------
__global__ void __launch_bounds__(256)
ln_final(const float* __restrict__ gamma, const float* __restrict__ beta,
         float* __restrict__ out)
{
    const int t  = threadIdx.x;
    const int g  = t >> 6;
    const int tx = t & 63;
    const int bn = blockIdx.x * 4 + g;

    const float s  = g_part[bn][0][0] + g_part[bn][1][0];
    const float s2 = g_part[bn][0][1] + g_part[bn][1][1];
    const float mu  = s * (1.f / D_NEW);
    const float var = s2 * (1.f / D_NEW) - mu * mu;
    const float rinv = rsqrtf(var + LN_EPS);

    float4 c = *(const float4*)(out + (size_t)bn * D_NEW + tx * 4);
    const float4 gv = *(const float4*)(gamma + tx * 4);
    const float4 bv = *(const float4*)(beta + tx * 4);
    float4 o;
    o.x = (c.x - mu) * rinv * gv.x + bv.x;
    o.y = (c.y - mu) * rinv * gv.y + bv.y;
    o.z = (c.z - mu) * rinv * gv.z + bv.z;
    o.w = (c.w - mu) * rinv * gv.w + bv.w;
    *(float4*)(out + (size_t)bn * D_NEW + tx * 4) = o;
}

// ------------------------- launch -------------------------
#define GEMM_DYN_BYTES 65536

extern "C" void kernel_launch(void* const* d_in, const int* in_sizes, int n_in,
                              void* d_out, int out_size)
{
    (void)in_sizes; (void)n_in; (void)out_size;
    const float* atom   = (const float*)d_in[0];
    const float* nbr    = (const float*)d_in[1];
    const float* smask  = (const float*)d_in[2];
    const float* amask  = (const float*)d_in[3];
    const float* Wa     = (const float*)d_in[4];
    const float* ba     = (const float*)d_in[5];
    const float* Wn     = (const float*)d_in[6];
    const float* bnb    = (const float*)d_in[7];
    const float* wal    = (const float*)d_in[8];
    const float* bal    = (const float*)d_in[9];
    const float* gamma  = (const float*)d_in[10];
    const float* beta   = (const float*)d_in[11];
    float* out = (float*)d_out;

    cudaFuncSetAttribute(gemm_h, cudaFuncAttributeMaxDynamicSharedMemorySize, GEMM_DYN_BYTES);
    cudaFuncSetAttribute(fused_e_attn, cudaFuncAttributeMaxDynamicSharedMemorySize, FDYN_BYTES);

    prep_w<<<((D_NBR + D_NEW) * 256 + 255) / 256, 256>>>(Wn, Wa);
    gemm_h<<<dim3(BN_TOT / 128, 2), 256, GEMM_DYN_BYTES>>>(atom, ba);
    fused_e_attn<<<(M_E / FM) * 2, 256, FDYN_BYTES>>>(nbr, bnb, smask, amask,
                                                      wal, bal, out);
    ln_final<<<BN_TOT / 4, 256>>>(gamma, beta, out);
}

// round 12
// speedup vs baseline: 1.0657x; 1.0008x over previous
#include <cuda_runtime.h>
#include <cuda_bf16.h>
#include <cstdint>

#define KQ     12
#define D_NBR  320
#define D_NEW  256
#define HQ     8
#define DKQ    32
#define LN_EPS 1e-5f
#define BN_TOT (64 * 128)          // 8192 atoms
#define M_E    (BN_TOT * KQ)       // 98304 neighbor rows
#define NC_E   (D_NBR / 32)        // 10 k-chunks (BK=32)
#define NC_H   (D_NEW / 32)        // 8 k-chunks
#define BLK_BYTES 16384            // Wa: one (128n x 32k) hi+lo image block
#define WNC_BYTES 32768            // Wn: one (256n x 32k) hi+lo image block

// ------------------------- device scratch -------------------------
__device__ __align__(16) unsigned char g_WnImg[NC_E * WNC_BYTES];          // 320 KB
__device__ __align__(16) unsigned char g_WaImg[2 * NC_H * BLK_BYTES];      // 256 KB
__device__ float g_h[(size_t)BN_TOT * 256];
__device__ float g_part[BN_TOT][2][2];     // per atom, per n-half: (sum, sumsq)

// ------------------------- helpers -------------------------
__device__ __forceinline__ uint32_t smem_u32(const void* p) {
    uint32_t a;
    asm("{ .reg .u64 t; cvta.to.shared.u64 t, %1; cvt.u32.u64 %0, t; }" : "=r"(a) : "l"(p));
    return a;
}
__device__ __forceinline__ void ldmx4(uint32_t* r, uint32_t addr) {
    asm volatile("ldmatrix.sync.aligned.m8n8.x4.shared.b16 {%0,%1,%2,%3}, [%4];"
        : "=r"(r[0]), "=r"(r[1]), "=r"(r[2]), "=r"(r[3]) : "r"(addr));
}
__device__ __forceinline__ void mma_bf16(float* d, const uint32_t* a, const uint32_t* b) {
    asm volatile(
        "mma.sync.aligned.m16n8k16.row.col.f32.bf16.bf16.f32 "
        "{%0,%1,%2,%3}, {%4,%5,%6,%7}, {%8,%9}, {%0,%1,%2,%3};"
        : "+f"(d[0]), "+f"(d[1]), "+f"(d[2]), "+f"(d[3])
        : "r"(a[0]), "r"(a[1]), "r"(a[2]), "r"(a[3]), "r"(b[0]), "r"(b[1]));
}
__device__ __forceinline__ void cp16(uint32_t saddr, const void* g) {
    asm volatile("cp.async.cg.shared.global [%0], [%1], 16;" :: "r"(saddr), "l"(g) : "memory");
}
#define CP_COMMIT() asm volatile("cp.async.commit_group;" ::: "memory")
#define CP_WAIT(n)  asm volatile("cp.async.wait_group %0;" :: "n"(n) : "memory")

// swizzled offset inside an (R rows x 32k) bf16 image (row-major rows of 64B)
__device__ __host__ __forceinline__ uint32_t swz(int r, int k) {
    return (uint32_t)(r * 64 + ((((k >> 3) ^ ((r >> 1) & 3))) << 4) + (k & 7) * 2);
}
__device__ __forceinline__ uint32_t pack_bf2(float a, float b) {
    __nv_bfloat162 p = __floats2bfloat162_rn(a, b);
    return *(uint32_t*)&p;
}

// ------------------------- prep: split W into bf16 hi/lo swizzled images -------------------------
__global__ void prep_w(const float* __restrict__ Wn, const float* __restrict__ Wa) {
    int i = blockIdx.x * blockDim.x + threadIdx.x;
    if (i < D_NBR * 256) {
        const int k = i >> 8, n = i & 255;
        const int kc = k >> 5, kl = k & 31;
        const float x = Wn[k * 256 + n];
        const __nv_bfloat16 hi = __float2bfloat16(x);
        const __nv_bfloat16 lo = __float2bfloat16(x - __bfloat162float(hi));
        unsigned char* base = g_WnImg + (size_t)kc * WNC_BYTES;
        const uint32_t off = swz(n, kl);
        *(__nv_bfloat16*)(base + off)         = hi;
        *(__nv_bfloat16*)(base + 16384 + off) = lo;
    } else if (i < (D_NBR + D_NEW) * 256) {
        const int idx = i - D_NBR * 256;
        const int k = idx >> 8, n = idx & 255;
        const int ntile = n >> 7, nl = n & 127, kc = k >> 5, kl = k & 31;
        const float x = Wa[k * 256 + n];
        const __nv_bfloat16 hi = __float2bfloat16(x);
        const __nv_bfloat16 lo = __float2bfloat16(x - __bfloat162float(hi));
        unsigned char* base = g_WaImg + (size_t)(ntile * NC_H + kc) * BLK_BYTES;
        const uint32_t off = swz(nl, kl);
        *(__nv_bfloat16*)(base + off)        = hi;
        *(__nv_bfloat16*)(base + 8192 + off) = lo;
    }
}

// ------------------------- h-GEMM (bf16x3 mma): g_h = atom @ Wa + ba -------------------------
__global__ void __launch_bounds__(256, 2)
gemm_h(const float* __restrict__ X, const float* __restrict__ bias)
{
    extern __shared__ unsigned char sm[];
    const int t = threadIdx.x;
    const int lane = t & 31, wid = t >> 5;
    const int m0 = blockIdx.x * 128;
    const int nblk = blockIdx.y;
    const int K = D_NEW, NC = NC_H;

    const uint32_t sA = smem_u32(sm);
    const uint32_t sB = sA + 32768;

    const int wm = (wid & 3) * 32;
    const int wn = (wid >> 2) * 64;
    const int laneMA  = (lane & 7) + ((lane >> 3) & 1) * 8;
    const int laneK8A = lane >> 4;
    const int laneNB  = (lane & 7) + ((lane >> 4) & 1) * 8;
    const int laneK8B = (lane >> 3) & 1;

    float acc[2][8][4];
    #pragma unroll
    for (int mt = 0; mt < 2; ++mt)
        #pragma unroll
        for (int ng = 0; ng < 8; ++ng)
            #pragma unroll
            for (int j = 0; j < 4; ++j) acc[mt][ng][j] = 0.f;

    const int srow = t >> 1, shalf = t & 1;
    const float* Xrow = X + (size_t)(m0 + srow) * K + shalf * 16;
    const uint32_t offH0 = swz(srow, shalf * 16);
    const uint32_t offH1 = swz(srow, shalf * 16 + 8);

    float4 pf[4];
    #define LDA(kc) do { \
        const float4* xp = (const float4*)(Xrow + (kc) * 32); \
        pf[0] = xp[0]; pf[1] = xp[1]; pf[2] = xp[2]; pf[3] = xp[3]; } while (0)

    #define CVTSTS(ab, lodelta) do { \
        uint4 hi0, lo0, hi1, lo1; \
        hi0.x = pack_bf2(pf[0].x, pf[0].y); hi0.y = pack_bf2(pf[0].z, pf[0].w); \
        hi0.z = pack_bf2(pf[1].x, pf[1].y); hi0.w = pack_bf2(pf[1].z, pf[1].w); \
        hi1.x = pack_bf2(pf[2].x, pf[2].y); hi1.y = pack_bf2(pf[2].z, pf[2].w); \
        hi1.z = pack_bf2(pf[3].x, pf[3].y); hi1.w = pack_bf2(pf[3].z, pf[3].w); \
        lo0.x = pack_bf2(pf[0].x - __bfloat162float(__float2bfloat16(pf[0].x)), \
                         pf[0].y - __bfloat162float(__float2bfloat16(pf[0].y))); \
        lo0.y = pack_bf2(pf[0].z - __bfloat162float(__float2bfloat16(pf[0].z)), \
                         pf[0].w - __bfloat162float(__float2bfloat16(pf[0].w))); \
        lo0.z = pack_bf2(pf[1].x - __bfloat162float(__float2bfloat16(pf[1].x)), \
                         pf[1].y - __bfloat162float(__float2bfloat16(pf[1].y))); \
        lo0.w = pack_bf2(pf[1].z - __bfloat162float(__float2bfloat16(pf[1].z)), \
                         pf[1].w - __bfloat162float(__float2bfloat16(pf[1].w))); \
        lo1.x = pack_bf2(pf[2].x - __bfloat162float(__float2bfloat16(pf[2].x)), \
                         pf[2].y - __bfloat162float(__float2bfloat16(pf[2].y))); \
        lo1.y = pack_bf2(pf[2].z - __bfloat162float(__float2bfloat16(pf[2].z)), \
                         pf[2].w - __bfloat162float(__float2bfloat16(pf[2].w))); \
        lo1.z = pack_bf2(pf[3].x - __bfloat162float(__float2bfloat16(pf[3].x)), \
                         pf[3].y - __bfloat162float(__float2bfloat16(pf[3].y))); \
        lo1.w = pack_bf2(pf[3].z - __bfloat162float(__float2bfloat16(pf[3].z)), \
                         pf[3].w - __bfloat162float(__float2bfloat16(pf[3].w))); \
        asm volatile("st.shared.v4.b32 [%0], {%1,%2,%3,%4};" :: "r"((ab) + offH0), \
            "r"(hi0.x), "r"(hi0.y), "r"(hi0.z), "r"(hi0.w) : "memory"); \
        asm volatile("st.shared.v4.b32 [%0], {%1,%2,%3,%4};" :: "r"((ab) + offH1), \
            "r"(hi1.x), "r"(hi1.y), "r"(hi1.z), "r"(hi1.w) : "memory"); \
        asm volatile("st.shared.v4.b32 [%0], {%1,%2,%3,%4};" :: "r"((ab) + (lodelta) + offH0), \
            "r"(lo0.x), "r"(lo0.y), "r"(lo0.z), "r"(lo0.w) : "memory"); \
        asm volatile("st.shared.v4.b32 [%0], {%1,%2,%3,%4};" :: "r"((ab) + (lodelta) + offH1), \
            "r"(lo1.x), "r"(lo1.y), "r"(lo1.z), "r"(lo1.w) : "memory"); } while (0)

    #define CPB(kc, st) do { \
        const unsigned char* gsrc = g_WaImg + (size_t)((nblk * NC + (kc))) * BLK_BYTES + t * 16; \
        uint32_t sdst = sB + (st) * 16384 + t * 16; \
        cp16(sdst,          gsrc); \
        cp16(sdst + 4096,   gsrc + 4096); \
        cp16(sdst + 8192,   gsrc + 8192); \
        cp16(sdst + 12288,  gsrc + 12288); } while (0)

    LDA(0);
    CPB(0, 0); CP_COMMIT();
    CVTSTS(sA, 8192);

    for (int kc = 0; kc < NC; ++kc) {
        const int st = kc & 1;
        __syncthreads();
        if (kc + 1 < NC) {
            LDA(kc + 1);
            CPB(kc + 1, st ^ 1); CP_COMMIT();
            CP_WAIT(1);
        } else {
            CP_WAIT(0);
        }
        __syncthreads();

        const uint32_t aBase = sA + st * 16384;
        const uint32_t bBase = sB + st * 16384;
        #pragma unroll
        for (int ks = 0; ks < 2; ++ks) {
            uint32_t ah[2][4], al[2][4];
            #pragma unroll
            for (int mt = 0; mt < 2; ++mt) {
                const int m = wm + mt * 16 + laneMA;
                const int k8 = ks * 2 + laneK8A;
                const uint32_t off = (uint32_t)(m * 64 + ((k8 ^ ((m >> 1) & 3)) << 4));
                ldmx4(ah[mt], aBase + off);
                ldmx4(al[mt], aBase + 8192 + off);
            }
            #pragma unroll
            for (int nt = 0; nt < 4; ++nt) {
                uint32_t bh[4], bl[4];
                const int n = wn + nt * 16 + laneNB;
                const int k8 = ks * 2 + laneK8B;
                const uint32_t off = (uint32_t)(n * 64 + ((k8 ^ ((n >> 1) & 3)) << 4));
                ldmx4(bh, bBase + off);
                ldmx4(bl, bBase + 8192 + off);
                #pragma unroll
                for (int mt = 0; mt < 2; ++mt)
                    #pragma unroll
                    for (int half = 0; half < 2; ++half) {
                        float* a4 = acc[mt][nt * 2 + half];
                        mma_bf16(a4, ah[mt], &bh[half * 2]);
                        mma_bf16(a4, ah[mt], &bl[half * 2]);
                        mma_bf16(a4, al[mt], &bh[half * 2]);
                    }
            }
        }
        if (kc + 1 < NC) CVTSTS(sA + (st ^ 1) * 16384, 8192);
    }

    const int n0 = nblk * 128;
    #pragma unroll
    for (int mt = 0; mt < 2; ++mt) {
        const int r0 = m0 + wm + mt * 16 + (lane >> 2);
        #pragma unroll
        for (int ng = 0; ng < 8; ++ng) {
            const int c = n0 + wn + ng * 8 + (lane & 3) * 2;
            const float b0 = bias[c], b1 = bias[c + 1];
            float2 v0 = { acc[mt][ng][0] + b0, acc[mt][ng][1] + b1 };
            float2 v1 = { acc[mt][ng][2] + b0, acc[mt][ng][3] + b1 };
            *(float2*)(g_h + (size_t)r0 * 256 + c)       = v0;
            *(float2*)(g_h + (size_t)(r0 + 8) * 256 + c) = v1;
        }
    }
    #undef LDA
    #undef CVTSTS
    #undef CPB
}

// ------------------------- fused e-GEMM + attention (N=128 half) -------------------------
// CTA: M=96 rows (8 atoms) x N=128 (4 heads), 256 threads (8 warps, warp tile 48x32).
// 3-stage cp.async/STS pipeline, ONE __syncthreads per k-chunk.
// bid = mtile*2 + nblk  (halves adjacent -> co-scheduled -> nbr L2 reuse).
#define FM 96
#define ESTR 132
#define A_STG 12288                 // hi 6KB + lo 6KB
#define B_STG 16384                 // hi 8KB + lo 8KB
#define FDYN_BYTES (3 * A_STG + 3 * B_STG)   // 86016; e tile 96*132*4 = 50688 overlay

__global__ void __launch_bounds__(256, 2)
fused_e_attn(const float* __restrict__ nbr, const float* __restrict__ bnb,
             const float* __restrict__ smask, const float* __restrict__ amask,
             const float* __restrict__ wal, const float* __restrict__ bal,
             float* __restrict__ out)
{
    extern __shared__ unsigned char sm[];

    const int t = threadIdx.x;
    const int lane = t & 31, wid = t >> 5;
    const int bid = blockIdx.x;
    const int nblk = bid & 1;
    const int m0 = (bid >> 1) * FM;

    const uint32_t sA = smem_u32(sm);            // A: 3 stages x 12KB
    const uint32_t sB = sA + 3 * A_STG;          // B: 3 stages x 16KB
    float* s_e = (float*)sm;                     // epilogue overlay: 96 x 132 fp32

    const int wm = (wid & 1) * 48;               // 2 m-warps
    const int wn = (wid >> 1) * 32;              // 4 n-warps
    const int laneMA  = (lane & 7) + ((lane >> 3) & 1) * 8;
    const int laneK8A = lane >> 4;
    const int laneNB  = (lane & 7) + ((lane >> 4) & 1) * 8;
    const int laneK8B = (lane >> 3) & 1;

    float acc[3][4][4];
    #pragma unroll
    for (int mt = 0; mt < 3; ++mt)
        #pragma unroll
        for (int ng = 0; ng < 4; ++ng)
            #pragma unroll
            for (int j = 0; j < 4; ++j) acc[mt][ng][j] = 0.f;

    // A staging: threads t<192, 2 per row
    const int srow = t >> 1, shalf = t & 1;
    const bool stager = (t < 2 * FM);
    const float* Xrow = nbr + (size_t)(m0 + srow) * D_NBR + shalf * 16;
    const uint32_t offH0 = swz(srow, shalf * 16);
    const uint32_t offH1 = swz(srow, shalf * 16 + 8);

    float4 pf[4];
    #define FLDA(kc) do { if (stager) { \
        const float4* xp = (const float4*)(Xrow + (kc) * 32); \
        pf[0] = xp[0]; pf[1] = xp[1]; pf[2] = xp[2]; pf[3] = xp[3]; } } while (0)

    #define FCVTSTS(st) do { if (stager) { \
        uint32_t ab = sA + (st) * A_STG; \
        uint4 hi0, lo0, hi1, lo1; \
        hi0.x = pack_bf2(pf[0].x, pf[0].y); hi0.y = pack_bf2(pf[0].z, pf[0].w); \
        hi0.z = pack_bf2(pf[1].x, pf[1].y); hi0.w = pack_bf2(pf[1].z, pf[1].w); \
        hi1.x = pack_bf2(pf[2].x, pf[2].y); hi1.y = pack_bf2(pf[2].z, pf[2].w); \
        hi1.z = pack_bf2(pf[3].x, pf[3].y); hi1.w = pack_bf2(pf[3].z, pf[3].w); \
        lo0.x = pack_bf2(pf[0].x - __bfloat162float(__float2bfloat16(pf[0].x)), \
                         pf[0].y - __bfloat162float(__float2bfloat16(pf[0].y))); \
        lo0.y = pack_bf2(pf[0].z - __bfloat162float(__float2bfloat16(pf[0].z)), \
                         pf[0].w - __bfloat162float(__float2bfloat16(pf[0].w))); \
        lo0.z = pack_bf2(pf[1].x - __bfloat162float(__float2bfloat16(pf[1].x)), \
                         pf[1].y - __bfloat162float(__float2bfloat16(pf[1].y))); \
        lo0.w = pack_bf2(pf[1].z - __bfloat162float(__float2bfloat16(pf[1].z)), \
                         pf[1].w - __bfloat162float(__float2bfloat16(pf[1].w))); \
        lo1.x = pack_bf2(pf[2].x - __bfloat162float(__float2bfloat16(pf[2].x)), \
                         pf[2].y - __bfloat162float(__float2bfloat16(pf[2].y))); \
        lo1.y = pack_bf2(pf[2].z - __bfloat162float(__float2bfloat16(pf[2].z)), \
                         pf[2].w - __bfloat162float(__float2bfloat16(pf[2].w))); \
        lo1.z = pack_bf2(pf[3].x - __bfloat162float(__float2bfloat16(pf[3].x)), \
                         pf[3].y - __bfloat162float(__float2bfloat16(pf[3].y))); \
        lo1.w = pack_bf2(pf[3].z - __bfloat162float(__float2bfloat16(pf[3].z)), \
                         pf[3].w - __bfloat162float(__float2bfloat16(pf[3].w))); \
        asm volatile("st.shared.v4.b32 [%0], {%1,%2,%3,%4};" :: "r"(ab + offH0), \
            "r"(hi0.x), "r"(hi0.y), "r"(hi0.z), "r"(hi0.w) : "memory"); \
        asm volatile("st.shared.v4.b32 [%0], {%1,%2,%3,%4};" :: "r"(ab + offH1), \
            "r"(hi1.x), "r"(hi1.y), "r"(hi1.z), "r"(hi1.w) : "memory"); \
        asm volatile("st.shared.v4.b32 [%0], {%1,%2,%3,%4};" :: "r"(ab + 6144 + offH0), \
            "r"(lo0.x), "r"(lo0.y), "r"(lo0.z), "r"(lo0.w) : "memory"); \
        asm volatile("st.shared.v4.b32 [%0], {%1,%2,%3,%4};" :: "r"(ab + 6144 + offH1), \
            "r"(lo1.x), "r"(lo1.y), "r"(lo1.z), "r"(lo1.w) : "memory"); } } while (0)

    // B: this CTA's 128-row slice of the 256-row image (rows are 64B, slice contiguous)
    #define FCPB(kc, st) do { \
        const unsigned char* hsrc = g_WnImg + (size_t)(kc) * WNC_BYTES + nblk * 8192 + t * 16; \
        const unsigned char* lsrc = hsrc + 16384; \
        uint32_t sdst = sB + (st) * B_STG + t * 16; \
        cp16(sdst,          hsrc); \
        cp16(sdst + 4096,   hsrc + 4096); \
        cp16(sdst + 8192,   lsrc); \
        cp16(sdst + 12288,  lsrc + 4096); } while (0)

    // ---- prologue: A[0] staged directly; A[1] in regs; B[0], B[1] in flight ----
    FLDA(0);
    FCVTSTS(0);
    FLDA(1);
    FCPB(0, 0); CP_COMMIT();
    FCPB(1, 1); CP_COMMIT();

    int cur = 0;                       // stage of chunk kc
    for (int kc = 0; kc < NC_E; ++kc) {
        // wait for B[kc] (allow B[kc+1] in flight), then one barrier
        if (kc + 1 < NC_E) { CP_WAIT(1); } else { CP_WAIT(0); }
        __syncthreads();               // B[kc]/A[kc] visible; all reads of slot (kc+2)%3, (kc+1)%3 done

        const int nxt1 = (cur + 1 == 3) ? 0 : cur + 1;
        const int nxt2 = (cur + 2 >= 3) ? cur - 1 : cur + 2;
        if (kc + 2 < NC_E) { FCPB(kc + 2, nxt2); CP_COMMIT(); }
        if (kc + 1 < NC_E) FCVTSTS(nxt1);          // store A[kc+1]

        const uint32_t aBase = sA + cur * A_STG;
        const uint32_t bBase = sB + cur * B_STG;
        #pragma unroll
        for (int ks = 0; ks < 2; ++ks) {
            uint32_t ah[3][4], al[3][4];
            #pragma unroll
            for (int mt = 0; mt < 3; ++mt) {
                const int m = wm + mt * 16 + laneMA;
                const int k8 = ks * 2 + laneK8A;
                const uint32_t off = (uint32_t)(m * 64 + ((k8 ^ ((m >> 1) & 3)) << 4));
                ldmx4(ah[mt], aBase + off);
                ldmx4(al[mt], aBase + 6144 + off);
            }
            #pragma unroll
            for (int nt = 0; nt < 2; ++nt) {
                uint32_t bh[4], bl[4];
                const int n = wn + nt * 16 + laneNB;
                const int k8 = ks * 2 + laneK8B;
                const uint32_t off = (uint32_t)(n * 64 + ((k8 ^ ((n >> 1) & 3)) << 4));
                ldmx4(bh, bBase + off);
                ldmx4(bl, bBase + 8192 + off);
                #pragma unroll
                for (int mt = 0; mt < 3; ++mt)
                    #pragma unroll
                    for (int half = 0; half < 2; ++half) {
                        float* a4 = acc[mt][nt * 2 + half];
                        mma_bf16(a4, ah[mt], &bh[half * 2]);
                        mma_bf16(a4, ah[mt], &bl[half * 2]);
                        mma_bf16(a4, al[mt], &bh[half * 2]);
                    }
            }
        }
        if (kc + 2 < NC_E) FLDA(kc + 2);           // prefetch A[kc+2] into regs
        cur = nxt1;
    }

    // ---- epilogue 1: acc + bias -> smem e tile (96 x 128, local cols) ----
    __syncthreads();                      // all ldmatrix reads done; s_e overlays stages
    #pragma unroll
    for (int mt = 0; mt < 3; ++mt) {
        const int r0 = wm + mt * 16 + (lane >> 2);
        #pragma unroll
        for (int ng = 0; ng < 4; ++ng) {
            const int c = wn + ng * 8 + (lane & 3) * 2;     // local col 0..127
            const int cg = nblk * 128 + c;                  // global col
            const float b0 = __ldg(bnb + cg), b1 = __ldg(bnb + cg + 1);
            float2 v0 = { acc[mt][ng][0] + b0, acc[mt][ng][1] + b1 };
            float2 v1 = { acc[mt][ng][2] + b0, acc[mt][ng][3] + b1 };
            *(float2*)(s_e + (size_t)r0 * ESTR + c)       = v0;
            *(float2*)(s_e + (size_t)(r0 + 8) * ESTR + c) = v1;
        }
    }
    __syncthreads();

    // ---- epilogue 2: attention + softmax + ctx; warp = atom (32 threads x 4 cols = 128) ----
    {
        const int g  = wid;                // atom in CTA (0..7), one warp each
        const int bn = (bid >> 1) * 8 + g;
        const int colg = nblk * 128 + lane * 4;

        const float4 h4 = *(const float4*)(g_h + (size_t)bn * 256 + colg);
        const float4 w4 = *(const float4*)(wal + ((lane * 4) & 31));
        float4 e4[KQ];
        #pragma unroll
        for (int k = 0; k < KQ; ++k)
            e4[k] = *(const float4*)(s_e + (size_t)(g * KQ + k) * ESTR + lane * 4);
        const float bal0 = __ldg(bal);

        float sc[KQ];
        #pragma unroll
        for (int k = 0; k < KQ; ++k) {
            float x, s = 0.f;
            x = h4.x + e4[k].x; x = fmaxf(x, 0.01f * x); s = fmaf(x, w4.x, s);
            x = h4.y + e4[k].y; x = fmaxf(x, 0.01f * x); s = fmaf(x, w4.y, s);
            x = h4.z + e4[k].z; x = fmaxf(x, 0.01f * x); s = fmaf(x, w4.z, s);
            x = h4.w + e4[k].w; x = fmaxf(x, 0.01f * x); s = fmaf(x, w4.w, s);
            sc[k] = s;
        }
        #pragma unroll
        for (int o = 1; o < 8; o <<= 1)
            #pragma unroll
            for (int k = 0; k < KQ; ++k)
                sc[k] += __shfl_xor_sync(0xffffffffu, sc[k], o);

        float mx = -3.4e38f;
        #pragma unroll
        for (int k = 0; k < KQ; ++k) {
            sc[k] += bal0 + __ldg(smask + bn * KQ + k);
            mx = fmaxf(mx, sc[k]);
        }
        float sum = 0.f;
        #pragma unroll
        for (int k = 0; k < KQ; ++k) { sc[k] = __expf(sc[k] - mx); sum += sc[k]; }
        const float inv = 1.f / sum;
        #pragma unroll
        for (int k = 0; k < KQ; ++k) sc[k] = sc[k] * inv * __ldg(amask + bn * KQ + k);

        float c0 = 0.f, c1 = 0.f, c2 = 0.f, c3 = 0.f;
        #pragma unroll
        for (int k = 0; k < KQ; ++k) {
            c0 = fmaf(sc[k], e4[k].x, c0);
            c1 = fmaf(sc[k], e4[k].y, c1);
            c2 = fmaf(sc[k], e4[k].z, c2);
            c3 = fmaf(sc[k], e4[k].w, c3);
        }

        // LN partials over this 128-col half (full warp reduce)
        float v  = c0 + c1 + c2 + c3;
        float v2 = c0 * c0 + c1 * c1 + c2 * c2 + c3 * c3;
        #pragma unroll
        for (int o = 16; o > 0; o >>= 1) {
            v  += __shfl_xor_sync(0xffffffffu, v, o);
            v2 += __shfl_xor_sync(0xffffffffu, v2, o);
        }
        if (lane == 0) { g_part[bn][nblk][0] = v; g_part[bn][nblk][1] = v2; }

        float4 o;
        o.x = c0; o.y = c1; o.z = c2; o.w = c3;
        *(float4*)(out + (size_t)bn * D_NEW + colg) = o;
    }
    #undef FLDA
    #undef FCVTSTS
    #undef FCPB
}

// ------------------------- LN finish: normalize out in place -------------------------
__global__ void __launch_bounds__(256)
ln_final(const float* __restrict__ gamma, const float* __restrict__ beta,
         float* __restrict__ out)
{
    const int t  = threadIdx.x;
    const int g  = t >> 6;
    const int tx = t & 63;
    const int bn = blockIdx.x * 4 + g;

    const float s  = g_part[bn][0][0] + g_part[bn][1][0];
    const float s2 = g_part[bn][0][1] + g_part[bn][1][1];
    const float mu  = s * (1.f / D_NEW);
    const float var = s2 * (1.f / D_NEW) - mu * mu;
    const float rinv = rsqrtf(var + LN_EPS);

    float4 c = *(const float4*)(out + (size_t)bn * D_NEW + tx * 4);
    const float4 gv = *(const float4*)(gamma + tx * 4);
    const float4 bv = *(const float4*)(beta + tx * 4);
    float4 o;
    o.x = (c.x - mu) * rinv * gv.x + bv.x;
    o.y = (c.y - mu) * rinv * gv.y + bv.y;
    o.z = (c.z - mu) * rinv * gv.z + bv.z;
    o.w = (c.w - mu) * rinv * gv.w + bv.w;
    *(float4*)(out + (size_t)bn * D_NEW + tx * 4) = o;
}

// ------------------------- launch -------------------------
#define GEMM_DYN_BYTES 65536

extern "C" void kernel_launch(void* const* d_in, const int* in_sizes, int n_in,
                              void* d_out, int out_size)
{
    (void)in_sizes; (void)n_in; (void)out_size;
    const float* atom   = (const float*)d_in[0];
    const float* nbr    = (const float*)d_in[1];
    const float* smask  = (const float*)d_in[2];
    const float* amask  = (const float*)d_in[3];
    const float* Wa     = (const float*)d_in[4];
    const float* ba     = (const float*)d_in[5];
    const float* Wn     = (const float*)d_in[6];
    const float* bnb    = (const float*)d_in[7];
    const float* wal    = (const float*)d_in[8];
    const float* bal    = (const float*)d_in[9];
    const float* gamma  = (const float*)d_in[10];
    const float* beta   = (const float*)d_in[11];
    float* out = (float*)d_out;

    cudaFuncSetAttribute(gemm_h, cudaFuncAttributeMaxDynamicSharedMemorySize, GEMM_DYN_BYTES);
    cudaFuncSetAttribute(fused_e_attn, cudaFuncAttributeMaxDynamicSharedMemorySize, FDYN_BYTES);

    prep_w<<<((D_NBR + D_NEW) * 256 + 255) / 256, 256>>>(Wn, Wa);
    gemm_h<<<dim3(BN_TOT / 128, 2), 256, GEMM_DYN_BYTES>>>(atom, ba);
    fused_e_attn<<<(M_E / FM) * 2, 256, FDYN_BYTES>>>(nbr, bnb, smask, amask,
                                                      wal, bal, out);
    ln_final<<<BN_TOT / 4, 256>>>(gamma, beta, out);
}

// round 13
// speedup vs baseline: 1.0905x; 1.0232x over previous
#include <cuda_runtime.h>
#include <cuda_bf16.h>
#include <cstdint>

#define KQ     12
#define D_NBR  320
#define D_NEW  256
#define HQ     8
#define DKQ    32
#define LN_EPS 1e-5f
#define BN_TOT (64 * 128)          // 8192 atoms
#define M_E    (BN_TOT * KQ)       // 98304 neighbor rows
#define NC_E   (D_NBR / 32)        // 10 k-chunks (BK=32)
#define NC_H   (D_NEW / 32)        // 8 k-chunks
#define BLK_BYTES 16384            // Wa: one (128n x 32k) hi+lo image block
#define WNC_BYTES 32768            // Wn: one (256n x 32k) hi+lo image block

// ------------------------- device scratch -------------------------
__device__ __align__(16) unsigned char g_WnImg[NC_E * WNC_BYTES];          // 320 KB
__device__ __align__(16) unsigned char g_WaImg[2 * NC_H * BLK_BYTES];      // 256 KB
__device__ float g_h[(size_t)BN_TOT * 256];
__device__ float g_part[BN_TOT][2][2];     // per atom, per n-half: (sum, sumsq)

// ------------------------- helpers -------------------------
__device__ __forceinline__ uint32_t smem_u32(const void* p) {
    uint32_t a;
    asm("{ .reg .u64 t; cvta.to.shared.u64 t, %1; cvt.u32.u64 %0, t; }" : "=r"(a) : "l"(p));
    return a;
}
__device__ __forceinline__ void ldmx4(uint32_t* r, uint32_t addr) {
    asm volatile("ldmatrix.sync.aligned.m8n8.x4.shared.b16 {%0,%1,%2,%3}, [%4];"
        : "=r"(r[0]), "=r"(r[1]), "=r"(r[2]), "=r"(r[3]) : "r"(addr));
}
// non-volatile: register-only deps, lets the compiler/ptxas interleave MMAs
__device__ __forceinline__ void mma_bf16(float* d, const uint32_t* a, const uint32_t* b) {
    asm("mma.sync.aligned.m16n8k16.row.col.f32.bf16.bf16.f32 "
        "{%0,%1,%2,%3}, {%4,%5,%6,%7}, {%8,%9}, {%0,%1,%2,%3};"
        : "+f"(d[0]), "+f"(d[1]), "+f"(d[2]), "+f"(d[3])
        : "r"(a[0]), "r"(a[1]), "r"(a[2]), "r"(a[3]), "r"(b[0]), "r"(b[1]));
}
__device__ __forceinline__ void cp16(uint32_t saddr, const void* g) {
    asm volatile("cp.async.cg.shared.global [%0], [%1], 16;" :: "r"(saddr), "l"(g) : "memory");
}
#define CP_COMMIT() asm volatile("cp.async.commit_group;" ::: "memory")
#define CP_WAIT(n)  asm volatile("cp.async.wait_group %0;" :: "n"(n) : "memory")

// swizzled offset inside an (R rows x 32k) bf16 image (row-major rows of 64B)
__device__ __host__ __forceinline__ uint32_t swz(int r, int k) {
    return (uint32_t)(r * 64 + ((((k >> 3) ^ ((r >> 1) & 3))) << 4) + (k & 7) * 2);
}
__device__ __forceinline__ uint32_t pack_bf2(float a, float b) {
    __nv_bfloat162 p = __floats2bfloat162_rn(a, b);
    return *(uint32_t*)&p;
}

// ------------------------- prep: split W into bf16 hi/lo swizzled images -------------------------
__global__ void prep_w(const float* __restrict__ Wn, const float* __restrict__ Wa) {
    int i = blockIdx.x * blockDim.x + threadIdx.x;
    if (i < D_NBR * 256) {
        const int k = i >> 8, n = i & 255;
        const int kc = k >> 5, kl = k & 31;
        const float x = Wn[k * 256 + n];
        const __nv_bfloat16 hi = __float2bfloat16(x);
        const __nv_bfloat16 lo = __float2bfloat16(x - __bfloat162float(hi));
        unsigned char* base = g_WnImg + (size_t)kc * WNC_BYTES;
        const uint32_t off = swz(n, kl);
        *(__nv_bfloat16*)(base + off)         = hi;
        *(__nv_bfloat16*)(base + 16384 + off) = lo;
    } else if (i < (D_NBR + D_NEW) * 256) {
        const int idx = i - D_NBR * 256;
        const int k = idx >> 8, n = idx & 255;
        const int ntile = n >> 7, nl = n & 127, kc = k >> 5, kl = k & 31;
        const float x = Wa[k * 256 + n];
        const __nv_bfloat16 hi = __float2bfloat16(x);
        const __nv_bfloat16 lo = __float2bfloat16(x - __bfloat162float(hi));
        unsigned char* base = g_WaImg + (size_t)(ntile * NC_H + kc) * BLK_BYTES;
        const uint32_t off = swz(nl, kl);
        *(__nv_bfloat16*)(base + off)        = hi;
        *(__nv_bfloat16*)(base + 8192 + off) = lo;
    }
}

// ------------------------- h-GEMM (bf16x3 mma): g_h = atom @ Wa + ba -------------------------
__global__ void __launch_bounds__(256, 2)
gemm_h(const float* __restrict__ X, const float* __restrict__ bias)
{
    extern __shared__ unsigned char sm[];
    const int t = threadIdx.x;
    const int lane = t & 31, wid = t >> 5;
    const int m0 = blockIdx.x * 128;
    const int nblk = blockIdx.y;
    const int K = D_NEW, NC = NC_H;

    const uint32_t sA = smem_u32(sm);
    const uint32_t sB = sA + 32768;

    const int wm = (wid & 3) * 32;
    const int wn = (wid >> 2) * 64;
    const int laneMA  = (lane & 7) + ((lane >> 3) & 1) * 8;
    const int laneK8A = lane >> 4;
    const int laneNB  = (lane & 7) + ((lane >> 4) & 1) * 8;
    const int laneK8B = (lane >> 3) & 1;

    float acc[2][8][4];
    #pragma unroll
    for (int mt = 0; mt < 2; ++mt)
        #pragma unroll
        for (int ng = 0; ng < 8; ++ng)
            #pragma unroll
            for (int j = 0; j < 4; ++j) acc[mt][ng][j] = 0.f;

    const int srow = t >> 1, shalf = t & 1;
    const float* Xrow = X + (size_t)(m0 + srow) * K + shalf * 16;
    const uint32_t offH0 = swz(srow, shalf * 16);
    const uint32_t offH1 = swz(srow, shalf * 16 + 8);

    float4 pf[4];
    #define LDA(kc) do { \
        const float4* xp = (const float4*)(Xrow + (kc) * 32); \
        pf[0] = xp[0]; pf[1] = xp[1]; pf[2] = xp[2]; pf[3] = xp[3]; } while (0)

    #define CVTSTS(ab, lodelta) do { \
        uint4 hi0, lo0, hi1, lo1; \
        hi0.x = pack_bf2(pf[0].x, pf[0].y); hi0.y = pack_bf2(pf[0].z, pf[0].w); \
        hi0.z = pack_bf2(pf[1].x, pf[1].y); hi0.w = pack_bf2(pf[1].z, pf[1].w); \
        hi1.x = pack_bf2(pf[2].x, pf[2].y); hi1.y = pack_bf2(pf[2].z, pf[2].w); \
        hi1.z = pack_bf2(pf[3].x, pf[3].y); hi1.w = pack_bf2(pf[3].z, pf[3].w); \
        lo0.x = pack_bf2(pf[0].x - __bfloat162float(__float2bfloat16(pf[0].x)), \
                         pf[0].y - __bfloat162float(__float2bfloat16(pf[0].y))); \
        lo0.y = pack_bf2(pf[0].z - __bfloat162float(__float2bfloat16(pf[0].z)), \
                         pf[0].w - __bfloat162float(__float2bfloat16(pf[0].w))); \
        lo0.z = pack_bf2(pf[1].x - __bfloat162float(__float2bfloat16(pf[1].x)), \
                         pf[1].y - __bfloat162float(__float2bfloat16(pf[1].y))); \
        lo0.w = pack_bf2(pf[1].z - __bfloat162float(__float2bfloat16(pf[1].z)), \
                         pf[1].w - __bfloat162float(__float2bfloat16(pf[1].w))); \
        lo1.x = pack_bf2(pf[2].x - __bfloat162float(__float2bfloat16(pf[2].x)), \
                         pf[2].y - __bfloat162float(__float2bfloat16(pf[2].y))); \
        lo1.y = pack_bf2(pf[2].z - __bfloat162float(__float2bfloat16(pf[2].z)), \
                         pf[2].w - __bfloat162float(__float2bfloat16(pf[2].w))); \
        lo1.z = pack_bf2(pf[3].x - __bfloat162float(__float2bfloat16(pf[3].x)), \
                         pf[3].y - __bfloat162float(__float2bfloat16(pf[3].y))); \
        lo1.w = pack_bf2(pf[3].z - __bfloat162float(__float2bfloat16(pf[3].z)), \
                         pf[3].w - __bfloat162float(__float2bfloat16(pf[3].w))); \
        asm volatile("st.shared.v4.b32 [%0], {%1,%2,%3,%4};" :: "r"((ab) + offH0), \
            "r"(hi0.x), "r"(hi0.y), "r"(hi0.z), "r"(hi0.w) : "memory"); \
        asm volatile("st.shared.v4.b32 [%0], {%1,%2,%3,%4};" :: "r"((ab) + offH1), \
            "r"(hi1.x), "r"(hi1.y), "r"(hi1.z), "r"(hi1.w) : "memory"); \
        asm volatile("st.shared.v4.b32 [%0], {%1,%2,%3,%4};" :: "r"((ab) + (lodelta) + offH0), \
            "r"(lo0.x), "r"(lo0.y), "r"(lo0.z), "r"(lo0.w) : "memory"); \
        asm volatile("st.shared.v4.b32 [%0], {%1,%2,%3,%4};" :: "r"((ab) + (lodelta) + offH1), \
            "r"(lo1.x), "r"(lo1.y), "r"(lo1.z), "r"(lo1.w) : "memory"); } while (0)

    #define CPB(kc, st) do { \
        const unsigned char* gsrc = g_WaImg + (size_t)((nblk * NC + (kc))) * BLK_BYTES + t * 16; \
        uint32_t sdst = sB + (st) * 16384 + t * 16; \
        cp16(sdst,          gsrc); \
        cp16(sdst + 4096,   gsrc + 4096); \
        cp16(sdst + 8192,   gsrc + 8192); \
        cp16(sdst + 12288,  gsrc + 12288); } while (0)

    LDA(0);
    CPB(0, 0); CP_COMMIT();
    CVTSTS(sA, 8192);

    for (int kc = 0; kc < NC; ++kc) {
        const int st = kc & 1;
        __syncthreads();
        if (kc + 1 < NC) {
            LDA(kc + 1);
            CPB(kc + 1, st ^ 1); CP_COMMIT();
            CP_WAIT(1);
        } else {
            CP_WAIT(0);
        }
        __syncthreads();

        const uint32_t aBase = sA + st * 16384;
        const uint32_t bBase = sB + st * 16384;
        #pragma unroll
        for (int ks = 0; ks < 2; ++ks) {
            uint32_t ah[2][4], al[2][4];
            #pragma unroll
            for (int mt = 0; mt < 2; ++mt) {
                const int m = wm + mt * 16 + laneMA;
                const int k8 = ks * 2 + laneK8A;
                const uint32_t off = (uint32_t)(m * 64 + ((k8 ^ ((m >> 1) & 3)) << 4));
                ldmx4(ah[mt], aBase + off);
                ldmx4(al[mt], aBase + 8192 + off);
            }
            #pragma unroll
            for (int nt = 0; nt < 4; ++nt) {
                uint32_t bh[4], bl[4];
                const int n = wn + nt * 16 + laneNB;
                const int k8 = ks * 2 + laneK8B;
                const uint32_t off = (uint32_t)(n * 64 + ((k8 ^ ((n >> 1) & 3)) << 4));
                ldmx4(bh, bBase + off);
                ldmx4(bl, bBase + 8192 + off);
                #pragma unroll
                for (int mt = 0; mt < 2; ++mt)
                    #pragma unroll
                    for (int half = 0; half < 2; ++half) {
                        float* a4 = acc[mt][nt * 2 + half];
                        mma_bf16(a4, ah[mt], &bh[half * 2]);
                        mma_bf16(a4, ah[mt], &bl[half * 2]);
                        mma_bf16(a4, al[mt], &bh[half * 2]);
                    }
            }
        }
        if (kc + 1 < NC) CVTSTS(sA + (st ^ 1) * 16384, 8192);
    }

    const int n0 = nblk * 128;
    #pragma unroll
    for (int mt = 0; mt < 2; ++mt) {
        const int r0 = m0 + wm + mt * 16 + (lane >> 2);
        #pragma unroll
        for (int ng = 0; ng < 8; ++ng) {
            const int c = n0 + wn + ng * 8 + (lane & 3) * 2;
            const float b0 = bias[c], b1 = bias[c + 1];
            float2 v0 = { acc[mt][ng][0] + b0, acc[mt][ng][1] + b1 };
            float2 v1 = { acc[mt][ng][2] + b0, acc[mt][ng][3] + b1 };
            *(float2*)(g_h + (size_t)r0 * 256 + c)       = v0;
            *(float2*)(g_h + (size_t)(r0 + 8) * 256 + c) = v1;
        }
    }
    #undef LDA
    #undef CVTSTS
    #undef CPB
}

// ------------------------- fused e-GEMM + attention (N=128 half) -------------------------
// CTA: M=96 rows (8 atoms) x N=128 (4 heads), 256 threads (8 warps, warp tile 48x32).
// A: 3-stage STS pipeline; B: 4-stage cp.async pipeline (B[kc+1..kc+3] in flight).
// One __syncthreads per k-chunk; A-convert burst buried between the two MMA half-phases.
#define FM 96
#define ESTR 132
#define A_STG 12288                 // hi 6KB + lo 6KB
#define B_STG 16384                 // hi 8KB + lo 8KB
#define FDYN_BYTES (3 * A_STG + 4 * B_STG)   // 102400; e tile 96*132*4 = 50688 overlay

__global__ void __launch_bounds__(256, 2)
fused_e_attn(const float* __restrict__ nbr, const float* __restrict__ bnb,
             const float* __restrict__ smask, const float* __restrict__ amask,
             const float* __restrict__ wal, const float* __restrict__ bal,
             float* __restrict__ out)
{
    extern __shared__ unsigned char sm[];

    const int t = threadIdx.x;
    const int lane = t & 31, wid = t >> 5;
    const int bid = blockIdx.x;
    const int nblk = bid & 1;
    const int m0 = (bid >> 1) * FM;

    const uint32_t sA = smem_u32(sm);            // A: 3 stages x 12KB
    const uint32_t sB = sA + 3 * A_STG;          // B: 4 stages x 16KB
    float* s_e = (float*)sm;                     // epilogue overlay: 96 x 132 fp32

    const int wm = (wid & 1) * 48;               // 2 m-warps
    const int wn = (wid >> 1) * 32;              // 4 n-warps
    const int laneMA  = (lane & 7) + ((lane >> 3) & 1) * 8;
    const int laneK8A = lane >> 4;
    const int laneNB  = (lane & 7) + ((lane >> 4) & 1) * 8;
    const int laneK8B = (lane >> 3) & 1;

    float acc[3][4][4];
    #pragma unroll
    for (int mt = 0; mt < 3; ++mt)
        #pragma unroll
        for (int ng = 0; ng < 4; ++ng)
            #pragma unroll
            for (int j = 0; j < 4; ++j) acc[mt][ng][j] = 0.f;

    // A staging: threads t<192, 2 per row
    const int srow = t >> 1, shalf = t & 1;
    const bool stager = (t < 2 * FM);
    const float* Xrow = nbr + (size_t)(m0 + srow) * D_NBR + shalf * 16;
    const uint32_t offH0 = swz(srow, shalf * 16);
    const uint32_t offH1 = swz(srow, shalf * 16 + 8);

    float4 pf[4];
    #define FLDA(kc) do { if (stager) { \
        const float4* xp = (const float4*)(Xrow + (kc) * 32); \
        pf[0] = xp[0]; pf[1] = xp[1]; pf[2] = xp[2]; pf[3] = xp[3]; } } while (0)

    #define FCVTSTS(st) do { if (stager) { \
        uint32_t ab = sA + (st) * A_STG; \
        uint4 hi0, lo0, hi1, lo1; \
        hi0.x = pack_bf2(pf[0].x, pf[0].y); hi0.y = pack_bf2(pf[0].z, pf[0].w); \
        hi0.z = pack_bf2(pf[1].x, pf[1].y); hi0.w = pack_bf2(pf[1].z, pf[1].w); \
        hi1.x = pack_bf2(pf[2].x, pf[2].y); hi1.y = pack_bf2(pf[2].z, pf[2].w); \
        hi1.z = pack_bf2(pf[3].x, pf[3].y); hi1.w = pack_bf2(pf[3].z, pf[3].w); \
        lo0.x = pack_bf2(pf[0].x - __bfloat162float(__float2bfloat16(pf[0].x)), \
                         pf[0].y - __bfloat162float(__float2bfloat16(pf[0].y))); \
        lo0.y = pack_bf2(pf[0].z - __bfloat162float(__float2bfloat16(pf[0].z)), \
                         pf[0].w - __bfloat162float(__float2bfloat16(pf[0].w))); \
        lo0.z = pack_bf2(pf[1].x - __bfloat162float(__float2bfloat16(pf[1].x)), \
                         pf[1].y - __bfloat162float(__float2bfloat16(pf[1].y))); \
        lo0.w = pack_bf2(pf[1].z - __bfloat162float(__float2bfloat16(pf[1].z)), \
                         pf[1].w - __bfloat162float(__float2bfloat16(pf[1].w))); \
        lo1.x = pack_bf2(pf[2].x - __bfloat162float(__float2bfloat16(pf[2].x)), \
                         pf[2].y - __bfloat162float(__float2bfloat16(pf[2].y))); \
        lo1.y = pack_bf2(pf[2].z - __bfloat162float(__float2bfloat16(pf[2].z)), \
                         pf[2].w - __bfloat162float(__float2bfloat16(pf[2].w))); \
        lo1.z = pack_bf2(pf[3].x - __bfloat162float(__float2bfloat16(pf[3].x)), \
                         pf[3].y - __bfloat162float(__float2bfloat16(pf[3].y))); \
        lo1.w = pack_bf2(pf[3].z - __bfloat162float(__float2bfloat16(pf[3].z)), \
                         pf[3].w - __bfloat162float(__float2bfloat16(pf[3].w))); \
        asm volatile("st.shared.v4.b32 [%0], {%1,%2,%3,%4};" :: "r"(ab + offH0), \
            "r"(hi0.x), "r"(hi0.y), "r"(hi0.z), "r"(hi0.w) : "memory"); \
        asm volatile("st.shared.v4.b32 [%0], {%1,%2,%3,%4};" :: "r"(ab + offH1), \
            "r"(hi1.x), "r"(hi1.y), "r"(hi1.z), "r"(hi1.w) : "memory"); \
        asm volatile("st.shared.v4.b32 [%0], {%1,%2,%3,%4};" :: "r"(ab + 6144 + offH0), \
            "r"(lo0.x), "r"(lo0.y), "r"(lo0.z), "r"(lo0.w) : "memory"); \
        asm volatile("st.shared.v4.b32 [%0], {%1,%2,%3,%4};" :: "r"(ab + 6144 + offH1), \
            "r"(lo1.x), "r"(lo1.y), "r"(lo1.z), "r"(lo1.w) : "memory"); } } while (0)

    // B: this CTA's 128-row slice of the 256-row image (rows are 64B, slice contiguous)
    #define FCPB(kc, st) do { \
        const unsigned char* hsrc = g_WnImg + (size_t)(kc) * WNC_BYTES + nblk * 8192 + t * 16; \
        const unsigned char* lsrc = hsrc + 16384; \
        uint32_t sdst = sB + (st) * B_STG + t * 16; \
        cp16(sdst,          hsrc); \
        cp16(sdst + 4096,   hsrc + 4096); \
        cp16(sdst + 8192,   lsrc); \
        cp16(sdst + 12288,  lsrc + 4096); } while (0)

    // ---- prologue: A[0] staged; A[1] in regs; B[0..2] in flight ----
    FLDA(0);
    FCVTSTS(0);
    FLDA(1);
    FCPB(0, 0); CP_COMMIT();
    FCPB(1, 1); CP_COMMIT();
    FCPB(2, 2); CP_COMMIT();

    int acur = 0;                      // A stage of chunk kc (mod 3)
    for (int kc = 0; kc < NC_E; ++kc) {
        // B[kc] must be complete; allow up to 2 newer groups in flight
        if (kc <= NC_E - 3)      { CP_WAIT(2); }
        else if (kc == NC_E - 2) { CP_WAIT(1); }
        else                     { CP_WAIT(0); }
        __syncthreads();               // B[kc]/A[kc] visible; old-slot readers all past

        const int anxt = (acur + 1 == 3) ? 0 : acur + 1;
        if (kc + 3 < NC_E) { FCPB(kc + 3, (kc + 3) & 3); CP_COMMIT(); }

        const uint32_t aBase = sA + acur * A_STG;
        const uint32_t bBase = sB + (kc & 3) * B_STG;

        #pragma unroll
        for (int ks = 0; ks < 2; ++ks) {
            uint32_t ah[3][4], al[3][4];
            #pragma unroll
            for (int mt = 0; mt < 3; ++mt) {
                const int m = wm + mt * 16 + laneMA;
                const int k8 = ks * 2 + laneK8A;
                const uint32_t off = (uint32_t)(m * 64 + ((k8 ^ ((m >> 1) & 3)) << 4));
                ldmx4(ah[mt], aBase + off);
                ldmx4(al[mt], aBase + 6144 + off);
            }
            #pragma unroll
            for (int nt = 0; nt < 2; ++nt) {
                uint32_t bh[4], bl[4];
                const int n = wn + nt * 16 + laneNB;
                const int k8 = ks * 2 + laneK8B;
                const uint32_t off = (uint32_t)(n * 64 + ((k8 ^ ((n >> 1) & 3)) << 4));
                ldmx4(bh, bBase + off);
                ldmx4(bl, bBase + 8192 + off);
                #pragma unroll
                for (int mt = 0; mt < 3; ++mt)
                    #pragma unroll
                    for (int half = 0; half < 2; ++half) {
                        float* a4 = acc[mt][nt * 2 + half];
                        mma_bf16(a4, ah[mt], &bh[half * 2]);
                        mma_bf16(a4, ah[mt], &bl[half * 2]);
                        mma_bf16(a4, al[mt], &bh[half * 2]);
                    }
            }
            // bury the A-convert burst in the shadow of the first MMA half-phase
            if (ks == 0 && kc + 1 < NC_E) FCVTSTS(anxt);
        }
        if (kc + 2 < NC_E) FLDA(kc + 2);           // prefetch A[kc+2] into regs
        acur = anxt;
    }

    // ---- epilogue 1: acc + bias -> smem e tile (96 x 128, local cols) ----
    __syncthreads();                      // all ldmatrix reads done; s_e overlays stages
    #pragma unroll
    for (int mt = 0; mt < 3; ++mt) {
        const int r0 = wm + mt * 16 + (lane >> 2);
        #pragma unroll
        for (int ng = 0; ng < 4; ++ng) {
            const int c = wn + ng * 8 + (lane & 3) * 2;     // local col 0..127
            const int cg = nblk * 128 + c;                  // global col
            const float b0 = __ldg(bnb + cg), b1 = __ldg(bnb + cg + 1);
            float2 v0 = { acc[mt][ng][0] + b0, acc[mt][ng][1] + b1 };
            float2 v1 = { acc[mt][ng][2] + b0, acc[mt][ng][3] + b1 };
            *(float2*)(s_e + (size_t)r0 * ESTR + c)       = v0;
            *(float2*)(s_e + (size_t)(r0 + 8) * ESTR + c) = v1;
        }
    }
    __syncthreads();

    // ---- epilogue 2: attention + softmax + ctx; warp = atom (32 threads x 4 cols = 128) ----
    {
        const int g  = wid;                // atom in CTA (0..7), one warp each
        const int bn = (bid >> 1) * 8 + g;
        const int colg = nblk * 128 + lane * 4;

        const float4 h4 = *(const float4*)(g_h + (size_t)bn * 256 + colg);
        const float4 w4 = *(const float4*)(wal + ((lane * 4) & 31));
        float4 e4[KQ];
        #pragma unroll
        for (int k = 0; k < KQ; ++k)
            e4[k] = *(const float4*)(s_e + (size_t)(g * KQ + k) * ESTR + lane * 4);
        const float bal0 = __ldg(bal);

        float sc[KQ];
        #pragma unroll
        for (int k = 0; k < KQ; ++k) {
            float x, s = 0.f;
            x = h4.x + e4[k].x; x = fmaxf(x, 0.01f * x); s = fmaf(x, w4.x, s);
            x = h4.y + e4[k].y; x = fmaxf(x, 0.01f * x); s = fmaf(x, w4.y, s);
            x = h4.z + e4[k].z; x = fmaxf(x, 0.01f * x); s = fmaf(x, w4.z, s);
            x = h4.w + e4[k].w; x = fmaxf(x, 0.01f * x); s = fmaf(x, w4.w, s);
            sc[k] = s;
        }
        #pragma unroll
        for (int o = 1; o < 8; o <<= 1)
            #pragma unroll
            for (int k = 0; k < KQ; ++k)
                sc[k] += __shfl_xor_sync(0xffffffffu, sc[k], o);

        float mx = -3.4e38f;
        #pragma unroll
        for (int k = 0; k < KQ; ++k) {
            sc[k] += bal0 + __ldg(smask + bn * KQ + k);
            mx = fmaxf(mx, sc[k]);
        }
        float sum = 0.f;
        #pragma unroll
        for (int k = 0; k < KQ; ++k) { sc[k] = __expf(sc[k] - mx); sum += sc[k]; }
        const float inv = 1.f / sum;
        #pragma unroll
        for (int k = 0; k < KQ; ++k) sc[k] = sc[k] * inv * __ldg(amask + bn * KQ + k);

        float c0 = 0.f, c1 = 0.f, c2 = 0.f, c3 = 0.f;
        #pragma unroll
        for (int k = 0; k < KQ; ++k) {
            c0 = fmaf(sc[k], e4[k].x, c0);
            c1 = fmaf(sc[k], e4[k].y, c1);
            c2 = fmaf(sc[k], e4[k].z, c2);
            c3 = fmaf(sc[k], e4[k].w, c3);
        }

        // LN partials over this 128-col half (full warp reduce)
        float v  = c0 + c1 + c2 + c3;
        float v2 = c0 * c0 + c1 * c1 + c2 * c2 + c3 * c3;
        #pragma unroll
        for (int o = 16; o > 0; o >>= 1) {
            v  += __shfl_xor_sync(0xffffffffu, v, o);
            v2 += __shfl_xor_sync(0xffffffffu, v2, o);
        }
        if (lane == 0) { g_part[bn][nblk][0] = v; g_part[bn][nblk][1] = v2; }

        float4 o;
        o.x = c0; o.y = c1; o.z = c2; o.w = c3;
        *(float4*)(out + (size_t)bn * D_NEW + colg) = o;
    }
    #undef FLDA
    #undef FCVTSTS
    #undef FCPB
}

// ------------------------- LN finish: normalize out in place -------------------------
__global__ void __launch_bounds__(256)
ln_final(const float* __restrict__ gamma, const float* __restrict__ beta,
         float* __restrict__ out)
{
    const int t  = threadIdx.x;
    const int g  = t >> 6;
    const int tx = t & 63;
    const int bn = blockIdx.x * 4 + g;

    const float s  = g_part[bn][0][0] + g_part[bn][1][0];
    const float s2 = g_part[bn][0][1] + g_part[bn][1][1];
    const float mu  = s * (1.f / D_NEW);
    const float var = s2 * (1.f / D_NEW) - mu * mu;
    const float rinv = rsqrtf(var + LN_EPS);

    float4 c = *(const float4*)(out + (size_t)bn * D_NEW + tx * 4);
    const float4 gv = *(const float4*)(gamma + tx * 4);
    const float4 bv = *(const float4*)(beta + tx * 4);
    float4 o;
    o.x = (c.x - mu) * rinv * gv.x + bv.x;
    o.y = (c.y - mu) * rinv * gv.y + bv.y;
    o.z = (c.z - mu) * rinv * gv.z + bv.z;
    o.w = (c.w - mu) * rinv * gv.w + bv.w;
    *(float4*)(out + (size_t)bn * D_NEW + tx * 4) = o;
}

// ------------------------- launch -------------------------
#define GEMM_DYN_BYTES 65536

extern "C" void kernel_launch(void* const* d_in, const int* in_sizes, int n_in,
                              void* d_out, int out_size)
{
    (void)in_sizes; (void)n_in; (void)out_size;
    const float* atom   = (const float*)d_in[0];
    const float* nbr    = (const float*)d_in[1];
    const float* smask  = (const float*)d_in[2];
    const float* amask  = (const float*)d_in[3];
    const float* Wa     = (const float*)d_in[4];
    const float* ba     = (const float*)d_in[5];
    const float* Wn     = (const float*)d_in[6];
    const float* bnb    = (const float*)d_in[7];
    const float* wal    = (const float*)d_in[8];
    const float* bal    = (const float*)d_in[9];
    const float* gamma  = (const float*)d_in[10];
    const float* beta   = (const float*)d_in[11];
    float* out = (float*)d_out;

    cudaFuncSetAttribute(gemm_h, cudaFuncAttributeMaxDynamicSharedMemorySize, GEMM_DYN_BYTES);
    cudaFuncSetAttribute(fused_e_attn, cudaFuncAttributeMaxDynamicSharedMemorySize, FDYN_BYTES);

    prep_w<<<((D_NBR + D_NEW) * 256 + 255) / 256, 256>>>(Wn, Wa);
    gemm_h<<<dim3(BN_TOT / 128, 2), 256, GEMM_DYN_BYTES>>>(atom, ba);
    fused_e_attn<<<(M_E / FM) * 2, 256, FDYN_BYTES>>>(nbr, bnb, smask, amask,
                                                      wal, bal, out);
    ln_final<<<BN_TOT / 4, 256>>>(gamma, beta, out);
}